// round 1
// baseline (speedup 1.0000x reference)
#include <cuda_runtime.h>

#define BATCH 8
#define LQn 2048
#define LKn 2048
#define DIMn 1024

// Scratch (static device globals -- no runtime allocation).
__device__ float g_S[(size_t)BATCH * LQn * LKn];   // logits / probs, 134 MB
__device__ float g_Q[(size_t)BATCH * LQn * DIMn];  // input * dot_scale, 67 MB

// ---------------------------------------------------------------------------
// Pass 0: Q = input * dot_scale (elementwise, column-broadcast scale)
// ---------------------------------------------------------------------------
__global__ __launch_bounds__(256) void scale_kernel(const float* __restrict__ input,
                                                    const float* __restrict__ scale) {
    size_t i = ((size_t)blockIdx.x * 256 + threadIdx.x) * 4;
    float4 v = *(const float4*)(input + i);
    float4 s = *(const float4*)(scale + (i & (DIMn - 1)));
    v.x *= s.x; v.y *= s.y; v.z *= s.z; v.w *= s.w;
    *(float4*)(g_Q + i) = v;
}

// Shared-tile store helper for the A/B "row-major, K-contiguous" loaders:
// thread loads rows (lrow, lrow+64), cols lcol..lcol+3, stores transposed.
#define ST_TRANS(SM, nb, v0, v1)                                             \
    SM[nb][lcol + 0][lrow] = v0.x;  SM[nb][lcol + 1][lrow] = v0.y;           \
    SM[nb][lcol + 2][lrow] = v0.z;  SM[nb][lcol + 3][lrow] = v0.w;           \
    SM[nb][lcol + 0][lrow + 64] = v1.x; SM[nb][lcol + 1][lrow + 64] = v1.y;  \
    SM[nb][lcol + 2][lrow + 64] = v1.z; SM[nb][lcol + 3][lrow + 64] = v1.w;

#define MICRO_MMA(buf)                                                       \
    _Pragma("unroll")                                                        \
    for (int kk = 0; kk < 16; kk++) {                                        \
        float4 a0 = *(const float4*)(&As[buf][kk][ty * 4]);                  \
        float4 a1 = *(const float4*)(&As[buf][kk][64 + ty * 4]);             \
        float4 b0 = *(const float4*)(&Bs[buf][kk][tx * 4]);                  \
        float4 b1 = *(const float4*)(&Bs[buf][kk][64 + tx * 4]);             \
        float af[8] = {a0.x, a0.y, a0.z, a0.w, a1.x, a1.y, a1.z, a1.w};      \
        float bf[8] = {b0.x, b0.y, b0.z, b0.w, b1.x, b1.y, b1.z, b1.w};      \
        _Pragma("unroll")                                                    \
        for (int i = 0; i < 8; i++)                                          \
            _Pragma("unroll")                                                \
            for (int j = 0; j < 8; j++)                                      \
                acc[i][j] = fmaf(af[i], bf[j], acc[i][j]);                   \
    }

// ---------------------------------------------------------------------------
// Pass 1: S[b] = Q[b] @ memory[b]^T - 1e30 * mask  (NT GEMM, 128x128x16 tile)
// ---------------------------------------------------------------------------
__global__ __launch_bounds__(256, 2) void qk_kernel(const float* __restrict__ memory,
                                                    const float* __restrict__ mask) {
    const int b = blockIdx.z;
    const int m0 = blockIdx.y * 128;
    const int n0 = blockIdx.x * 128;
    const float* A  = g_Q + (size_t)b * LQn * DIMn;
    const float* Bm = memory + (size_t)b * LKn * DIMn;

    __shared__ float As[2][16][132];
    __shared__ float Bs[2][16][132];

    const int tid  = threadIdx.x;
    const int lrow = tid >> 2;          // 0..63
    const int lcol = (tid & 3) << 2;    // 0,4,8,12
    const int ty   = tid >> 4;          // 0..15
    const int tx   = tid & 15;          // 0..15

    const float* Aptr = A  + (size_t)(m0 + lrow) * DIMn + lcol;
    const float* Bptr = Bm + (size_t)(n0 + lrow) * DIMn + lcol;

    float acc[8][8];
#pragma unroll
    for (int i = 0; i < 8; i++)
#pragma unroll
        for (int j = 0; j < 8; j++) acc[i][j] = 0.0f;

    float4 ra0 = *(const float4*)(Aptr);
    float4 ra1 = *(const float4*)(Aptr + 64 * DIMn);
    float4 rb0 = *(const float4*)(Bptr);
    float4 rb1 = *(const float4*)(Bptr + 64 * DIMn);
    ST_TRANS(As, 0, ra0, ra1)
    ST_TRANS(Bs, 0, rb0, rb1)
    __syncthreads();

    int buf = 0;
    const int NT = DIMn / 16;  // 64
    for (int kt = 0; kt < NT; kt++) {
        if (kt + 1 < NT) {
            const float* Ap = Aptr + (kt + 1) * 16;
            const float* Bp = Bptr + (kt + 1) * 16;
            ra0 = *(const float4*)(Ap);
            ra1 = *(const float4*)(Ap + 64 * DIMn);
            rb0 = *(const float4*)(Bp);
            rb1 = *(const float4*)(Bp + 64 * DIMn);
        }
        MICRO_MMA(buf)
        if (kt + 1 < NT) {
            const int nb = buf ^ 1;
            ST_TRANS(As, nb, ra0, ra1)
            ST_TRANS(Bs, nb, rb0, rb1)
        }
        __syncthreads();
        buf ^= 1;
    }

    float* C = g_S + (size_t)b * LQn * LKn;
    float mk[8];
#pragma unroll
    for (int j = 0; j < 4; j++) {
        mk[j]     = mask[(size_t)b * LKn + n0 + tx * 4 + j];
        mk[4 + j] = mask[(size_t)b * LKn + n0 + 64 + tx * 4 + j];
    }
#pragma unroll
    for (int i = 0; i < 8; i++) {
        const int row = m0 + ((i < 4) ? (ty * 4 + i) : (64 + ty * 4 + (i - 4)));
        float* cr = C + (size_t)row * LKn + n0;
        float4 v0, v1;
        v0.x = acc[i][0] - 1e30f * mk[0];
        v0.y = acc[i][1] - 1e30f * mk[1];
        v0.z = acc[i][2] - 1e30f * mk[2];
        v0.w = acc[i][3] - 1e30f * mk[3];
        v1.x = acc[i][4] - 1e30f * mk[4];
        v1.y = acc[i][5] - 1e30f * mk[5];
        v1.z = acc[i][6] - 1e30f * mk[6];
        v1.w = acc[i][7] - 1e30f * mk[7];
        *(float4*)(cr + tx * 4) = v0;
        *(float4*)(cr + 64 + tx * 4) = v1;
    }
}

// ---------------------------------------------------------------------------
// Pass 2: row softmax over the LK axis, in place in g_S. One CTA per row.
// ---------------------------------------------------------------------------
__global__ __launch_bounds__(256) void softmax_kernel() {
    float* p = g_S + (size_t)blockIdx.x * LKn;
    const int tid = threadIdx.x;

    float4 a = *(float4*)(p + tid * 8);
    float4 c = *(float4*)(p + tid * 8 + 4);

    float m = fmaxf(fmaxf(fmaxf(a.x, a.y), fmaxf(a.z, a.w)),
                    fmaxf(fmaxf(c.x, c.y), fmaxf(c.z, c.w)));
#pragma unroll
    for (int o = 16; o > 0; o >>= 1) m = fmaxf(m, __shfl_xor_sync(0xffffffffu, m, o));

    __shared__ float red[8];
    const int warp = tid >> 5;
    if ((tid & 31) == 0) red[warp] = m;
    __syncthreads();
    m = red[0];
#pragma unroll
    for (int i = 1; i < 8; i++) m = fmaxf(m, red[i]);

    a.x = expf(a.x - m); a.y = expf(a.y - m); a.z = expf(a.z - m); a.w = expf(a.w - m);
    c.x = expf(c.x - m); c.y = expf(c.y - m); c.z = expf(c.z - m); c.w = expf(c.w - m);

    float s = (a.x + a.y) + (a.z + a.w) + (c.x + c.y) + (c.z + c.w);
#pragma unroll
    for (int o = 16; o > 0; o >>= 1) s += __shfl_xor_sync(0xffffffffu, s, o);

    __syncthreads();  // everyone done reading red (max) before reuse
    if ((tid & 31) == 0) red[warp] = s;
    __syncthreads();
    s = ((red[0] + red[1]) + (red[2] + red[3])) + ((red[4] + red[5]) + (red[6] + red[7]));

    const float inv = 1.0f / s;
    a.x *= inv; a.y *= inv; a.z *= inv; a.w *= inv;
    c.x *= inv; c.y *= inv; c.z *= inv; c.w *= inv;

    *(float4*)(p + tid * 8)     = a;
    *(float4*)(p + tid * 8 + 4) = c;
}

// ---------------------------------------------------------------------------
// Pass 3: O[b] = P[b] @ memory[b]  (NN GEMM, 128x128x16 tile)
// ---------------------------------------------------------------------------
__global__ __launch_bounds__(256, 2) void pv_kernel(const float* __restrict__ memory,
                                                    float* __restrict__ out) {
    const int b = blockIdx.z;
    const int m0 = blockIdx.y * 128;
    const int n0 = blockIdx.x * 128;
    const float* A  = g_S + (size_t)b * LQn * LKn;     // P: [LQ, LK]
    const float* Bm = memory + (size_t)b * LKn * DIMn; // V: [LK, D]

    __shared__ float As[2][16][132];
    __shared__ float Bs[2][16][132];

    const int tid  = threadIdx.x;
    const int lrow = tid >> 2;           // A loader: 0..63
    const int lcol = (tid & 3) << 2;
    const int krow = tid >> 5;           // B loader: k rows 0..7 (+8)
    const int bcol = (tid & 31) << 2;    // B loader: n cols 0..124
    const int ty   = tid >> 4;
    const int tx   = tid & 15;

    const float* Aptr = A  + (size_t)(m0 + lrow) * LKn + lcol;
    const float* Bptr = Bm + (size_t)krow * DIMn + n0 + bcol;

    float acc[8][8];
#pragma unroll
    for (int i = 0; i < 8; i++)
#pragma unroll
        for (int j = 0; j < 8; j++) acc[i][j] = 0.0f;

    float4 ra0 = *(const float4*)(Aptr);
    float4 ra1 = *(const float4*)(Aptr + 64 * LKn);
    float4 rb0 = *(const float4*)(Bptr);
    float4 rb1 = *(const float4*)(Bptr + 8 * DIMn);
    ST_TRANS(As, 0, ra0, ra1)
    *(float4*)(&Bs[0][krow][bcol])     = rb0;
    *(float4*)(&Bs[0][krow + 8][bcol]) = rb1;
    __syncthreads();

    int buf = 0;
    const int NT = LKn / 16;  // 128
    for (int kt = 0; kt < NT; kt++) {
        if (kt + 1 < NT) {
            const float* Ap = Aptr + (kt + 1) * 16;
            const float* Bp = Bptr + (size_t)(kt + 1) * 16 * DIMn;
            ra0 = *(const float4*)(Ap);
            ra1 = *(const float4*)(Ap + 64 * LKn);
            rb0 = *(const float4*)(Bp);
            rb1 = *(const float4*)(Bp + 8 * DIMn);
        }
        MICRO_MMA(buf)
        if (kt + 1 < NT) {
            const int nb = buf ^ 1;
            ST_TRANS(As, nb, ra0, ra1)
            *(float4*)(&Bs[nb][krow][bcol])     = rb0;
            *(float4*)(&Bs[nb][krow + 8][bcol]) = rb1;
        }
        __syncthreads();
        buf ^= 1;
    }

    float* Co = out + (size_t)b * LQn * DIMn;
#pragma unroll
    for (int i = 0; i < 8; i++) {
        const int row = m0 + ((i < 4) ? (ty * 4 + i) : (64 + ty * 4 + (i - 4)));
        float* cr = Co + (size_t)row * DIMn + n0;
        float4 v0, v1;
        v0.x = acc[i][0]; v0.y = acc[i][1]; v0.z = acc[i][2]; v0.w = acc[i][3];
        v1.x = acc[i][4]; v1.y = acc[i][5]; v1.z = acc[i][6]; v1.w = acc[i][7];
        *(float4*)(cr + tx * 4) = v0;
        *(float4*)(cr + 64 + tx * 4) = v1;
    }
}

// ---------------------------------------------------------------------------
// kernel_launch: input, memory, mask, w_input (unused: cancels in softmax),
// dot_scale. Output float32 [B, LQ, D].
// ---------------------------------------------------------------------------
extern "C" void kernel_launch(void* const* d_in, const int* in_sizes, int n_in,
                              void* d_out, int out_size) {
    const float* input     = (const float*)d_in[0];
    const float* memory    = (const float*)d_in[1];
    const float* mask      = (const float*)d_in[2];
    const float* dot_scale = (const float*)d_in[4];
    float* out = (float*)d_out;

    scale_kernel<<<(BATCH * LQn * DIMn) / (4 * 256), 256>>>(input, dot_scale);

    dim3 g1(LKn / 128, LQn / 128, BATCH);
    qk_kernel<<<g1, 256>>>(memory, mask);

    softmax_kernel<<<BATCH * LQn, 256>>>();

    dim3 g3(DIMn / 128, LQn / 128, BATCH);
    pv_kernel<<<g3, 256>>>(memory, out);
}

// round 3
// speedup vs baseline: 1.8392x; 1.8392x over previous
#include <cuda_runtime.h>
#include <cuda_bf16.h>
#include <cstdint>

#define B_  8
#define LQ_ 2048
#define LK_ 2048
#define D_  1024

// ---------------------------------------------------------------------------
// Static device scratch (no runtime allocation allowed)
// ---------------------------------------------------------------------------
__device__ __nv_bfloat16 g_Qh[(size_t)B_ * LQ_ * D_];   // (input*scale) hi
__device__ __nv_bfloat16 g_Ql[(size_t)B_ * LQ_ * D_];   // lo
__device__ __nv_bfloat16 g_Mh[(size_t)B_ * LK_ * D_];   // memory [LK,D] hi
__device__ __nv_bfloat16 g_Ml[(size_t)B_ * LK_ * D_];
__device__ __nv_bfloat16 g_MTh[(size_t)B_ * D_ * LK_];  // memory^T [D,LK] hi
__device__ __nv_bfloat16 g_MTl[(size_t)B_ * D_ * LK_];
__device__ __nv_bfloat16 g_Ph[(size_t)B_ * LQ_ * LK_];  // probs hi
__device__ __nv_bfloat16 g_Pl[(size_t)B_ * LQ_ * LK_];
__device__ float         g_S[(size_t)B_ * LQ_ * LK_];   // fp32 logits

// ---------------------------------------------------------------------------
// Helpers (base sm_103 ISA only: cp.async + ldmatrix + mma.sync)
// ---------------------------------------------------------------------------
__device__ __forceinline__ uint32_t smem_u32(const void* p) {
    uint32_t a;
    asm("{ .reg .u64 t; cvta.to.shared.u64 t, %1; cvt.u32.u64 %0, t; }" : "=r"(a) : "l"(p));
    return a;
}

__device__ __forceinline__ void cp16(uint32_t saddr, const void* gaddr) {
    asm volatile("cp.async.cg.shared.global [%0], [%1], 16;\n" :: "r"(saddr), "l"(gaddr));
}

__device__ __forceinline__ void ldsm4(uint32_t* r, uint32_t addr) {
    asm volatile("ldmatrix.sync.aligned.m8n8.x4.shared.b16 {%0,%1,%2,%3}, [%4];"
                 : "=r"(r[0]), "=r"(r[1]), "=r"(r[2]), "=r"(r[3]) : "r"(addr));
}

__device__ __forceinline__ void mma_bf16(float* c, const uint32_t* a, const uint32_t* b) {
    asm volatile("mma.sync.aligned.m16n8k16.row.col.f32.bf16.bf16.f32 "
                 "{%0,%1,%2,%3}, {%4,%5,%6,%7}, {%8,%9}, {%0,%1,%2,%3};"
                 : "+f"(c[0]), "+f"(c[1]), "+f"(c[2]), "+f"(c[3])
                 : "r"(a[0]), "r"(a[1]), "r"(a[2]), "r"(a[3]), "r"(b[0]), "r"(b[1]));
}

__device__ __forceinline__ void split2(float v, __nv_bfloat16& h, __nv_bfloat16& l) {
    h = __float2bfloat16(v);
    l = __float2bfloat16(v - __bfloat162float(h));
}

// ---------------------------------------------------------------------------
// Conversion passes
// ---------------------------------------------------------------------------
__global__ __launch_bounds__(256) void qconv_kernel(const float* __restrict__ in,
                                                    const float* __restrict__ sc) {
    size_t i = ((size_t)blockIdx.x * 256 + threadIdx.x) * 8;
    float4 a = *(const float4*)(in + i);
    float4 b = *(const float4*)(in + i + 4);
    float4 s0 = *(const float4*)(sc + (i & (D_ - 1)));
    float4 s1 = *(const float4*)(sc + ((i + 4) & (D_ - 1)));
    float v[8] = {a.x * s0.x, a.y * s0.y, a.z * s0.z, a.w * s0.w,
                  b.x * s1.x, b.y * s1.y, b.z * s1.z, b.w * s1.w};
    __nv_bfloat16 h[8], l[8];
#pragma unroll
    for (int j = 0; j < 8; j++) split2(v[j], h[j], l[j]);
    *(uint4*)(g_Qh + i) = *(uint4*)h;
    *(uint4*)(g_Ql + i) = *(uint4*)l;
}

__global__ __launch_bounds__(256) void mconv_kernel(const float* __restrict__ mem) {
    size_t i = ((size_t)blockIdx.x * 256 + threadIdx.x) * 8;
    float4 a = *(const float4*)(mem + i);
    float4 b = *(const float4*)(mem + i + 4);
    float v[8] = {a.x, a.y, a.z, a.w, b.x, b.y, b.z, b.w};
    __nv_bfloat16 h[8], l[8];
#pragma unroll
    for (int j = 0; j < 8; j++) split2(v[j], h[j], l[j]);
    *(uint4*)(g_Mh + i) = *(uint4*)h;
    *(uint4*)(g_Ml + i) = *(uint4*)l;
}

// transpose memory [LK,D] -> [D,LK] bf16 hi/lo, 32x32 tiles
__global__ __launch_bounds__(256) void mtconv_kernel(const float* __restrict__ mem) {
    __shared__ float tile[32][33];
    const int d0 = blockIdx.x * 32;
    const int k0 = blockIdx.y * 32;
    const int bz = blockIdx.z;
    const int tx = threadIdx.x & 31;
    const int ty = threadIdx.x >> 5;  // 0..7
    const float* src = mem + (size_t)bz * LK_ * D_;
#pragma unroll
    for (int j = 0; j < 4; j++) {
        int kl = ty + j * 8;
        tile[kl][tx] = src[(size_t)(k0 + kl) * D_ + d0 + tx];
    }
    __syncthreads();
#pragma unroll
    for (int j = 0; j < 4; j++) {
        int dl = ty + j * 8;
        float v = tile[tx][dl];
        __nv_bfloat16 h, l;
        split2(v, h, l);
        size_t o = (size_t)bz * D_ * LK_ + (size_t)(d0 + dl) * LK_ + k0 + tx;
        g_MTh[o] = h;
        g_MTl[o] = l;
    }
}

// ---------------------------------------------------------------------------
// Split-bf16 warp-MMA GEMM.
// CTA tile 128(M) x 256(N), 8 warps (warp tile 64x64), K-chunk 32, 3 stages.
// D ~= Ah@Bh^T + Ah@Bl^T + Al@Bh^T  (fp32 accumulate)
// Smem rows padded to 80B: 16B-aligned, and r*80 mod 128 cycles all 8 slots
// over 8 consecutive rows -> conflict-free ldmatrix without XOR swizzle.
// ---------------------------------------------------------------------------
#define STG_A 10240                              // 128 rows * 80B
#define STG_B 20480                              // 256 rows * 80B
#define STAGE_BYTES (2 * STG_A + 2 * STG_B)      // 61440
#define NSTAGE 3
#define GEMM_SMEM (NSTAGE * STAGE_BYTES)         // 184320

template <bool QK>
__global__ __launch_bounds__(256, 1) void gemm_kernel(const float* __restrict__ mask,
                                                      float* __restrict__ outp) {
    constexpr int KDIM = QK ? D_ : LK_;      // contraction length
    constexpr int NDIM = QK ? LK_ : D_;      // output columns / B rows
    constexpr int NC   = KDIM / 32;          // K chunks

    extern __shared__ char smem_raw[];
    const uint32_t sb = smem_u32(smem_raw);

    const int t  = threadIdx.x;
    const int b  = blockIdx.z;
    const int m0 = blockIdx.y * 128;
    const int n0 = blockIdx.x * 256;

    const __nv_bfloat16* Ah = (QK ? g_Qh : g_Ph)  + ((size_t)b * LQ_  + m0) * KDIM;
    const __nv_bfloat16* Al = (QK ? g_Ql : g_Pl)  + ((size_t)b * LQ_  + m0) * KDIM;
    const __nv_bfloat16* Bh = (QK ? g_Mh : g_MTh) + ((size_t)b * NDIM + n0) * KDIM;
    const __nv_bfloat16* Bl = (QK ? g_Ml : g_MTl) + ((size_t)b * NDIM + n0) * KDIM;

    float acc[4][8][4];
#pragma unroll
    for (int i = 0; i < 4; i++)
#pragma unroll
        for (int j = 0; j < 8; j++)
#pragma unroll
            for (int k = 0; k < 4; k++) acc[i][j][k] = 0.0f;

    // ---- async loader: chunk c -> stage c%3 ----
    auto load_chunk = [&](int c) {
        const uint32_t st = sb + (c % NSTAGE) * STAGE_BYTES;
        const int koff = c * 32;
#pragma unroll
        for (int i = 0; i < 2; i++) {          // A: 128 rows * 4 x 16B chunks
            int id  = t + (i << 8);
            int row = id >> 2, ch = id & 3;
            uint32_t so = (uint32_t)(row * 80 + ch * 16);
            size_t   go = (size_t)row * KDIM + koff + ch * 8;
            cp16(st + so,         Ah + go);
            cp16(st + STG_A + so, Al + go);
        }
#pragma unroll
        for (int i = 0; i < 4; i++) {          // B: 256 rows * 4 x 16B chunks
            int id  = t + (i << 8);
            int row = id >> 2, ch = id & 3;
            uint32_t so = (uint32_t)(row * 80 + ch * 16);
            size_t   go = (size_t)row * KDIM + koff + ch * 8;
            cp16(st + 2 * STG_A + so,         Bh + go);
            cp16(st + 2 * STG_A + STG_B + so, Bl + go);
        }
        asm volatile("cp.async.commit_group;\n" ::: "memory");
    };

    const int lane = t & 31;
    const int w    = t >> 5;
    const int wm   = (w >> 2) * 64;   // warp M origin within CTA
    const int wn   = (w & 3) * 64;    // warp N origin within CTA

    // ldmatrix lane address components (see layout analysis in header comment)
    const int a_row   = wm + (lane & 15);
    const int a_khalf = lane >> 4;                       // 0/1 -> k+0 / k+8
    const int b_row   = wn + (lane & 7) + ((lane >> 4) << 3);
    const int b_khalf = (lane >> 3) & 1;

    load_chunk(0);
    load_chunk(1);
    load_chunk(2);

    for (int c = 0; c < NC; c++) {
        const int rem = NC - 1 - c;
        if (rem >= 2)      asm volatile("cp.async.wait_group 2;\n" ::: "memory");
        else if (rem == 1) asm volatile("cp.async.wait_group 1;\n" ::: "memory");
        else               asm volatile("cp.async.wait_group 0;\n" ::: "memory");
        __syncthreads();

        const uint32_t st   = sb + (c % NSTAGE) * STAGE_BYTES;
        const uint32_t stAh = st;
        const uint32_t stAl = st + STG_A;
        const uint32_t stBh = st + 2 * STG_A;
        const uint32_t stBl = st + 2 * STG_A + STG_B;

#pragma unroll
        for (int ks = 0; ks < 2; ks++) {
            uint32_t ah[4][4], al[4][4], bf[4][4];
            const uint32_t a_off = (uint32_t)(a_row * 80 + (ks * 2 + a_khalf) * 16);
            const uint32_t b_off = (uint32_t)(b_row * 80 + (ks * 2 + b_khalf) * 16);
#pragma unroll
            for (int i = 0; i < 4; i++) {
                ldsm4(ah[i], stAh + a_off + i * (16 * 80));
                ldsm4(al[i], stAl + a_off + i * (16 * 80));
            }
#pragma unroll
            for (int j = 0; j < 4; j++) ldsm4(bf[j], stBh + b_off + j * (16 * 80));
            // Ah*Bh + Al*Bh
#pragma unroll
            for (int i = 0; i < 4; i++)
#pragma unroll
                for (int jj = 0; jj < 8; jj++) {
                    const uint32_t* bp = &bf[jj >> 1][(jj & 1) * 2];
                    mma_bf16(acc[i][jj], ah[i], bp);
                    mma_bf16(acc[i][jj], al[i], bp);
                }
            // Ah*Bl
#pragma unroll
            for (int j = 0; j < 4; j++) ldsm4(bf[j], stBl + b_off + j * (16 * 80));
#pragma unroll
            for (int i = 0; i < 4; i++)
#pragma unroll
                for (int jj = 0; jj < 8; jj++)
                    mma_bf16(acc[i][jj], ah[i], &bf[jj >> 1][(jj & 1) * 2]);
        }

        __syncthreads();                    // all warps done before stage reuse
        if (c + NSTAGE < NC) load_chunk(c + NSTAGE);
    }

    // ---- epilogue ----
    float* Cbase = QK ? (g_S + (size_t)b * LQ_ * LK_) : (outp + (size_t)b * LQ_ * D_);
    const float* mrow = QK ? (mask + (size_t)b * LK_) : nullptr;

#pragma unroll
    for (int i = 0; i < 4; i++) {
        const int r0 = m0 + wm + i * 16 + (lane >> 2);
#pragma unroll
        for (int jj = 0; jj < 8; jj++) {
            const int col = n0 + wn + jj * 8 + (lane & 3) * 2;
            float v0 = acc[i][jj][0], v1 = acc[i][jj][1];
            float v2 = acc[i][jj][2], v3 = acc[i][jj][3];
            if (QK) {
                const float mk0 = 1e30f * __ldg(mrow + col);
                const float mk1 = 1e30f * __ldg(mrow + col + 1);
                v0 -= mk0; v1 -= mk1; v2 -= mk0; v3 -= mk1;
            }
            *(float2*)(Cbase + (size_t)r0 * NDIM + col)       = make_float2(v0, v1);
            *(float2*)(Cbase + (size_t)(r0 + 8) * NDIM + col) = make_float2(v2, v3);
        }
    }
}

// ---------------------------------------------------------------------------
// Softmax: fp32 logits row -> bf16 hi/lo probability row
// ---------------------------------------------------------------------------
__global__ __launch_bounds__(256) void softmax_kernel() {
    const float* p = g_S + (size_t)blockIdx.x * LK_;
    const int tid = threadIdx.x;

    float4 a = *(const float4*)(p + tid * 8);
    float4 c = *(const float4*)(p + tid * 8 + 4);

    float m = fmaxf(fmaxf(fmaxf(a.x, a.y), fmaxf(a.z, a.w)),
                    fmaxf(fmaxf(c.x, c.y), fmaxf(c.z, c.w)));
#pragma unroll
    for (int o = 16; o > 0; o >>= 1) m = fmaxf(m, __shfl_xor_sync(0xffffffffu, m, o));

    __shared__ float red[8];
    const int warp = tid >> 5;
    if ((tid & 31) == 0) red[warp] = m;
    __syncthreads();
    m = red[0];
#pragma unroll
    for (int i = 1; i < 8; i++) m = fmaxf(m, red[i]);

    a.x = expf(a.x - m); a.y = expf(a.y - m); a.z = expf(a.z - m); a.w = expf(a.w - m);
    c.x = expf(c.x - m); c.y = expf(c.y - m); c.z = expf(c.z - m); c.w = expf(c.w - m);

    float s = (a.x + a.y) + (a.z + a.w) + (c.x + c.y) + (c.z + c.w);
#pragma unroll
    for (int o = 16; o > 0; o >>= 1) s += __shfl_xor_sync(0xffffffffu, s, o);

    __syncthreads();
    if ((tid & 31) == 0) red[warp] = s;
    __syncthreads();
    s = ((red[0] + red[1]) + (red[2] + red[3])) + ((red[4] + red[5]) + (red[6] + red[7]));

    const float inv = 1.0f / s;
    float v[8] = {a.x * inv, a.y * inv, a.z * inv, a.w * inv,
                  c.x * inv, c.y * inv, c.z * inv, c.w * inv};
    __nv_bfloat16 h[8], l[8];
#pragma unroll
    for (int j = 0; j < 8; j++) split2(v[j], h[j], l[j]);
    size_t base = (size_t)blockIdx.x * LK_ + tid * 8;
    *(uint4*)(g_Ph + base) = *(uint4*)h;
    *(uint4*)(g_Pl + base) = *(uint4*)l;
}

// ---------------------------------------------------------------------------
// inputs: 0=input 1=memory 2=mask 3=w_input (cancels in softmax) 4=dot_scale
// ---------------------------------------------------------------------------
extern "C" void kernel_launch(void* const* d_in, const int* in_sizes, int n_in,
                              void* d_out, int out_size) {
    const float* input     = (const float*)d_in[0];
    const float* memory    = (const float*)d_in[1];
    const float* mask      = (const float*)d_in[2];
    const float* dot_scale = (const float*)d_in[4];
    float* out = (float*)d_out;

    cudaFuncSetAttribute(gemm_kernel<true>,  cudaFuncAttributeMaxDynamicSharedMemorySize, GEMM_SMEM);
    cudaFuncSetAttribute(gemm_kernel<false>, cudaFuncAttributeMaxDynamicSharedMemorySize, GEMM_SMEM);

    qconv_kernel<<<(size_t)B_ * LQ_ * D_ / 2048, 256>>>(input, dot_scale);
    mconv_kernel<<<(size_t)B_ * LK_ * D_ / 2048, 256>>>(memory);
    mtconv_kernel<<<dim3(D_ / 32, LK_ / 32, B_), 256>>>(memory);

    gemm_kernel<true><<<dim3(LK_ / 256, LQ_ / 128, B_), 256, GEMM_SMEM>>>(mask, nullptr);

    softmax_kernel<<<B_ * LQ_, 256>>>();

    gemm_kernel<false><<<dim3(D_ / 256, LQ_ / 128, B_), 256, GEMM_SMEM>>>(nullptr, out);
}

// round 4
// speedup vs baseline: 2.0218x; 1.0993x over previous
#include <cuda_runtime.h>
#include <cuda_bf16.h>
#include <cstdint>

#define B_  8
#define LQ_ 2048
#define LK_ 2048
#define D_  1024

// ---------------------------------------------------------------------------
// Static device scratch (no runtime allocation allowed)
// ---------------------------------------------------------------------------
__device__ __nv_bfloat16 g_Qh[(size_t)B_ * LQ_ * D_];   // (input*scale) hi
__device__ __nv_bfloat16 g_Ql[(size_t)B_ * LQ_ * D_];   // lo
__device__ __nv_bfloat16 g_Mh[(size_t)B_ * LK_ * D_];   // memory [LK,D] hi
__device__ __nv_bfloat16 g_Ml[(size_t)B_ * LK_ * D_];
__device__ __nv_bfloat16 g_MTh[(size_t)B_ * D_ * LK_];  // memory^T [D,LK] hi
__device__ __nv_bfloat16 g_MTl[(size_t)B_ * D_ * LK_];
__device__ __nv_bfloat16 g_Ph[(size_t)B_ * LQ_ * LK_];  // probs hi
__device__ __nv_bfloat16 g_Pl[(size_t)B_ * LQ_ * LK_];
__device__ float         g_S[(size_t)B_ * LQ_ * LK_];   // fp32 logits

// ---------------------------------------------------------------------------
// Helpers (base sm_103 ISA only: cp.async + ldmatrix + mma.sync)
// ---------------------------------------------------------------------------
__device__ __forceinline__ uint32_t smem_u32(const void* p) {
    uint32_t a;
    asm("{ .reg .u64 t; cvta.to.shared.u64 t, %1; cvt.u32.u64 %0, t; }" : "=r"(a) : "l"(p));
    return a;
}

__device__ __forceinline__ void cp16(uint32_t saddr, const void* gaddr) {
    asm volatile("cp.async.cg.shared.global [%0], [%1], 16;\n" :: "r"(saddr), "l"(gaddr));
}

__device__ __forceinline__ void ldsm4(uint32_t* r, uint32_t addr) {
    asm volatile("ldmatrix.sync.aligned.m8n8.x4.shared.b16 {%0,%1,%2,%3}, [%4];"
                 : "=r"(r[0]), "=r"(r[1]), "=r"(r[2]), "=r"(r[3]) : "r"(addr));
}

__device__ __forceinline__ void mma_bf16(float* c, const uint32_t* a, const uint32_t* b) {
    asm volatile("mma.sync.aligned.m16n8k16.row.col.f32.bf16.bf16.f32 "
                 "{%0,%1,%2,%3}, {%4,%5,%6,%7}, {%8,%9}, {%0,%1,%2,%3};"
                 : "+f"(c[0]), "+f"(c[1]), "+f"(c[2]), "+f"(c[3])
                 : "r"(a[0]), "r"(a[1]), "r"(a[2]), "r"(a[3]), "r"(b[0]), "r"(b[1]));
}

__device__ __forceinline__ void split2(float v, __nv_bfloat16& h, __nv_bfloat16& l) {
    h = __float2bfloat16(v);
    l = __float2bfloat16(v - __bfloat162float(h));
}

// ---------------------------------------------------------------------------
// Conversion passes
// ---------------------------------------------------------------------------
__global__ __launch_bounds__(256) void qconv_kernel(const float* __restrict__ in,
                                                    const float* __restrict__ sc) {
    size_t i = ((size_t)blockIdx.x * 256 + threadIdx.x) * 8;
    float4 a = *(const float4*)(in + i);
    float4 b = *(const float4*)(in + i + 4);
    float4 s0 = *(const float4*)(sc + (i & (D_ - 1)));
    float4 s1 = *(const float4*)(sc + ((i + 4) & (D_ - 1)));
    float v[8] = {a.x * s0.x, a.y * s0.y, a.z * s0.z, a.w * s0.w,
                  b.x * s1.x, b.y * s1.y, b.z * s1.z, b.w * s1.w};
    __nv_bfloat16 h[8], l[8];
#pragma unroll
    for (int j = 0; j < 8; j++) split2(v[j], h[j], l[j]);
    *(uint4*)(g_Qh + i) = *(uint4*)h;
    *(uint4*)(g_Ql + i) = *(uint4*)l;
}

__global__ __launch_bounds__(256) void mconv_kernel(const float* __restrict__ mem) {
    size_t i = ((size_t)blockIdx.x * 256 + threadIdx.x) * 8;
    float4 a = *(const float4*)(mem + i);
    float4 b = *(const float4*)(mem + i + 4);
    float v[8] = {a.x, a.y, a.z, a.w, b.x, b.y, b.z, b.w};
    __nv_bfloat16 h[8], l[8];
#pragma unroll
    for (int j = 0; j < 8; j++) split2(v[j], h[j], l[j]);
    *(uint4*)(g_Mh + i) = *(uint4*)h;
    *(uint4*)(g_Ml + i) = *(uint4*)l;
}

// transpose memory [LK,D] -> [D,LK] bf16 hi/lo, 32x32 tiles
__global__ __launch_bounds__(256) void mtconv_kernel(const float* __restrict__ mem) {
    __shared__ float tile[32][33];
    const int d0 = blockIdx.x * 32;
    const int k0 = blockIdx.y * 32;
    const int bz = blockIdx.z;
    const int tx = threadIdx.x & 31;
    const int ty = threadIdx.x >> 5;  // 0..7
    const float* src = mem + (size_t)bz * LK_ * D_;
#pragma unroll
    for (int j = 0; j < 4; j++) {
        int kl = ty + j * 8;
        tile[kl][tx] = src[(size_t)(k0 + kl) * D_ + d0 + tx];
    }
    __syncthreads();
#pragma unroll
    for (int j = 0; j < 4; j++) {
        int dl = ty + j * 8;
        float v = tile[tx][dl];
        __nv_bfloat16 h, l;
        split2(v, h, l);
        size_t o = (size_t)bz * D_ * LK_ + (size_t)(d0 + dl) * LK_ + k0 + tx;
        g_MTh[o] = h;
        g_MTl[o] = l;
    }
}

// ---------------------------------------------------------------------------
// Split-bf16 warp-MMA GEMM, round 4 layout:
//   CTA tile 128(M) x 256(N), 512 threads = 16 warps, warp tile 32x64.
//   K-chunk 64, 2 smem stages (221KB), term-separated MMA passes.
// D ~= Ah@Bh^T + Al@Bh^T + Ah@Bl^T  (fp32 accumulate)
// Rows padded to 144B: r*144 mod 128 cycles all 8 16B banks over 8 rows
// -> conflict-free ldmatrix without XOR swizzle.
// ---------------------------------------------------------------------------
#define ROWB  144
#define STG_A (128 * ROWB)                        // 18432
#define STG_B (256 * ROWB)                        // 36864
#define STAGE_BYTES (2 * STG_A + 2 * STG_B)       // 110592
#define NSTAGE 2
#define GEMM_SMEM (NSTAGE * STAGE_BYTES)          // 221184

template <bool QK>
__global__ __launch_bounds__(512, 1) void gemm_kernel(const float* __restrict__ mask,
                                                      float* __restrict__ outp) {
    constexpr int KDIM = QK ? D_ : LK_;      // contraction length
    constexpr int NDIM = QK ? LK_ : D_;      // output columns / B rows
    constexpr int NC   = KDIM / 64;          // K chunks

    extern __shared__ char smem_raw[];
    const uint32_t sb = smem_u32(smem_raw);

    const int t  = threadIdx.x;
    const int b  = blockIdx.z;
    const int m0 = blockIdx.y * 128;
    const int n0 = blockIdx.x * 256;

    const __nv_bfloat16* Ah = (QK ? g_Qh : g_Ph)  + ((size_t)b * LQ_  + m0) * KDIM;
    const __nv_bfloat16* Al = (QK ? g_Ql : g_Pl)  + ((size_t)b * LQ_  + m0) * KDIM;
    const __nv_bfloat16* Bh = (QK ? g_Mh : g_MTh) + ((size_t)b * NDIM + n0) * KDIM;
    const __nv_bfloat16* Bl = (QK ? g_Ml : g_MTl) + ((size_t)b * NDIM + n0) * KDIM;

    float acc[2][8][4];
#pragma unroll
    for (int i = 0; i < 2; i++)
#pragma unroll
        for (int j = 0; j < 8; j++)
#pragma unroll
            for (int k = 0; k < 4; k++) acc[i][j][k] = 0.0f;

    // ---- async loader: chunk c -> stage c%2, 64 k-elems = 8 x 16B per row ----
    auto load_chunk = [&](int c) {
        const uint32_t st = sb + (c & 1) * STAGE_BYTES;
        const int koff = c * 64;
#pragma unroll
        for (int i = 0; i < 2; i++) {          // A: 128 rows x 8 chunks (hi+lo)
            int id  = t + (i << 9);
            int row = id >> 3, ch = id & 7;
            uint32_t so = (uint32_t)(row * ROWB + ch * 16);
            size_t   go = (size_t)row * KDIM + koff + ch * 8;
            cp16(st + so,         Ah + go);
            cp16(st + STG_A + so, Al + go);
        }
#pragma unroll
        for (int i = 0; i < 4; i++) {          // B: 256 rows x 8 chunks (hi+lo)
            int id  = t + (i << 9);
            int row = id >> 3, ch = id & 7;
            uint32_t so = (uint32_t)(row * ROWB + ch * 16);
            size_t   go = (size_t)row * KDIM + koff + ch * 8;
            cp16(st + 2 * STG_A + so,         Bh + go);
            cp16(st + 2 * STG_A + STG_B + so, Bl + go);
        }
        asm volatile("cp.async.commit_group;\n" ::: "memory");
    };

    const int lane = t & 31;
    const int w    = t >> 5;           // 0..15
    const int wm   = (w >> 2) * 32;    // warp M origin (4 x 32)
    const int wn   = (w & 3) * 64;     // warp N origin (4 x 64)

    // ldmatrix lane addressing (layout proven in round 3)
    const int a_row   = wm + (lane & 15);
    const int a_khalf = lane >> 4;                       // 0/1 -> k+0 / k+8
    const int b_row   = wn + (lane & 7) + ((lane >> 4) << 3);
    const int b_khalf = (lane >> 3) & 1;

    load_chunk(0);
    if (NC > 1) load_chunk(1);

    for (int c = 0; c < NC; c++) {
        if (c + 1 < NC) asm volatile("cp.async.wait_group 1;\n" ::: "memory");
        else            asm volatile("cp.async.wait_group 0;\n" ::: "memory");
        __syncthreads();

        const uint32_t st   = sb + (c & 1) * STAGE_BYTES;
        const uint32_t stAh = st;
        const uint32_t stAl = st + STG_A;
        const uint32_t stBh = st + 2 * STG_A;
        const uint32_t stBl = st + 2 * STG_A + STG_B;

#pragma unroll
        for (int k16 = 0; k16 < 4; k16++) {
            uint32_t ah[2][4], al[2][4], bf[4][4];
            const uint32_t a_off = (uint32_t)(a_row * ROWB + k16 * 32 + a_khalf * 16);
            const uint32_t b_off = (uint32_t)(b_row * ROWB + k16 * 32 + b_khalf * 16);
#pragma unroll
            for (int i = 0; i < 2; i++) {
                ldsm4(ah[i], stAh + a_off + i * (16 * ROWB));
                ldsm4(al[i], stAl + a_off + i * (16 * ROWB));
            }
#pragma unroll
            for (int j = 0; j < 4; j++) ldsm4(bf[j], stBh + b_off + j * (16 * ROWB));

            // pass 1: Ah*Bh   (same-acc reuse distance = 16 MMAs)
#pragma unroll
            for (int i = 0; i < 2; i++)
#pragma unroll
                for (int jj = 0; jj < 8; jj++)
                    mma_bf16(acc[i][jj], ah[i], &bf[jj >> 1][(jj & 1) * 2]);
            // pass 2: Al*Bh
#pragma unroll
            for (int i = 0; i < 2; i++)
#pragma unroll
                for (int jj = 0; jj < 8; jj++)
                    mma_bf16(acc[i][jj], al[i], &bf[jj >> 1][(jj & 1) * 2]);
            // pass 3: Ah*Bl  (reload B frags in place)
#pragma unroll
            for (int j = 0; j < 4; j++) ldsm4(bf[j], stBl + b_off + j * (16 * ROWB));
#pragma unroll
            for (int i = 0; i < 2; i++)
#pragma unroll
                for (int jj = 0; jj < 8; jj++)
                    mma_bf16(acc[i][jj], ah[i], &bf[jj >> 1][(jj & 1) * 2]);
        }

        __syncthreads();                    // all warps done before stage reuse
        if (c + 2 < NC) load_chunk(c + 2);
    }

    // ---- epilogue ----
    float* Cbase = QK ? (g_S + (size_t)b * LQ_ * LK_) : (outp + (size_t)b * LQ_ * D_);
    const float* mrow = QK ? (mask + (size_t)b * LK_) : nullptr;

#pragma unroll
    for (int i = 0; i < 2; i++) {
        const int r0 = m0 + wm + i * 16 + (lane >> 2);
#pragma unroll
        for (int jj = 0; jj < 8; jj++) {
            const int col = n0 + wn + jj * 8 + (lane & 3) * 2;
            float v0 = acc[i][jj][0], v1 = acc[i][jj][1];
            float v2 = acc[i][jj][2], v3 = acc[i][jj][3];
            if (QK) {
                const float mk0 = 1e30f * __ldg(mrow + col);
                const float mk1 = 1e30f * __ldg(mrow + col + 1);
                v0 -= mk0; v1 -= mk1; v2 -= mk0; v3 -= mk1;
            }
            *(float2*)(Cbase + (size_t)r0 * NDIM + col)       = make_float2(v0, v1);
            *(float2*)(Cbase + (size_t)(r0 + 8) * NDIM + col) = make_float2(v2, v3);
        }
    }
}

// ---------------------------------------------------------------------------
// Softmax: fp32 logits row -> bf16 hi/lo probability row
// ---------------------------------------------------------------------------
__global__ __launch_bounds__(256) void softmax_kernel() {
    const float* p = g_S + (size_t)blockIdx.x * LK_;
    const int tid = threadIdx.x;

    float4 a = *(const float4*)(p + tid * 8);
    float4 c = *(const float4*)(p + tid * 8 + 4);

    float m = fmaxf(fmaxf(fmaxf(a.x, a.y), fmaxf(a.z, a.w)),
                    fmaxf(fmaxf(c.x, c.y), fmaxf(c.z, c.w)));
#pragma unroll
    for (int o = 16; o > 0; o >>= 1) m = fmaxf(m, __shfl_xor_sync(0xffffffffu, m, o));

    __shared__ float red[8];
    const int warp = tid >> 5;
    if ((tid & 31) == 0) red[warp] = m;
    __syncthreads();
    m = red[0];
#pragma unroll
    for (int i = 1; i < 8; i++) m = fmaxf(m, red[i]);

    a.x = expf(a.x - m); a.y = expf(a.y - m); a.z = expf(a.z - m); a.w = expf(a.w - m);
    c.x = expf(c.x - m); c.y = expf(c.y - m); c.z = expf(c.z - m); c.w = expf(c.w - m);

    float s = (a.x + a.y) + (a.z + a.w) + (c.x + c.y) + (c.z + c.w);
#pragma unroll
    for (int o = 16; o > 0; o >>= 1) s += __shfl_xor_sync(0xffffffffu, s, o);

    __syncthreads();
    if ((tid & 31) == 0) red[warp] = s;
    __syncthreads();
    s = ((red[0] + red[1]) + (red[2] + red[3])) + ((red[4] + red[5]) + (red[6] + red[7]));

    const float inv = 1.0f / s;
    float v[8] = {a.x * inv, a.y * inv, a.z * inv, a.w * inv,
                  c.x * inv, c.y * inv, c.z * inv, c.w * inv};
    __nv_bfloat16 h[8], l[8];
#pragma unroll
    for (int j = 0; j < 8; j++) split2(v[j], h[j], l[j]);
    size_t base = (size_t)blockIdx.x * LK_ + tid * 8;
    *(uint4*)(g_Ph + base) = *(uint4*)h;
    *(uint4*)(g_Pl + base) = *(uint4*)l;
}

// ---------------------------------------------------------------------------
// inputs: 0=input 1=memory 2=mask 3=w_input (cancels in softmax) 4=dot_scale
// ---------------------------------------------------------------------------
extern "C" void kernel_launch(void* const* d_in, const int* in_sizes, int n_in,
                              void* d_out, int out_size) {
    const float* input     = (const float*)d_in[0];
    const float* memory    = (const float*)d_in[1];
    const float* mask      = (const float*)d_in[2];
    const float* dot_scale = (const float*)d_in[4];
    float* out = (float*)d_out;

    cudaFuncSetAttribute(gemm_kernel<true>,  cudaFuncAttributeMaxDynamicSharedMemorySize, GEMM_SMEM);
    cudaFuncSetAttribute(gemm_kernel<false>, cudaFuncAttributeMaxDynamicSharedMemorySize, GEMM_SMEM);

    qconv_kernel<<<(size_t)B_ * LQ_ * D_ / 2048, 256>>>(input, dot_scale);
    mconv_kernel<<<(size_t)B_ * LK_ * D_ / 2048, 256>>>(memory);
    mtconv_kernel<<<dim3(D_ / 32, LK_ / 32, B_), 256>>>(memory);

    gemm_kernel<true><<<dim3(LK_ / 256, LQ_ / 128, B_), 512, GEMM_SMEM>>>(mask, nullptr);

    softmax_kernel<<<B_ * LQ_, 256>>>();

    gemm_kernel<false><<<dim3(D_ / 256, LQ_ / 128, B_), 512, GEMM_SMEM>>>(nullptr, out);
}

// round 5
// speedup vs baseline: 2.8209x; 1.3952x over previous
#include <cuda_runtime.h>
#include <cuda_fp16.h>
#include <cstdint>

#define B_  8
#define LQ_ 2048
#define LK_ 2048
#define D_  1024

// ---------------------------------------------------------------------------
// Static device scratch (no runtime allocation allowed)
// ---------------------------------------------------------------------------
__device__ __half g_Qh[(size_t)B_ * LQ_ * D_];   // (input*scale) hi
__device__ __half g_Ql[(size_t)B_ * LQ_ * D_];   // lo
__device__ __half g_Mh[(size_t)B_ * LK_ * D_];   // memory [LK,D] fp16
__device__ __half g_MTh[(size_t)B_ * D_ * LK_];  // memory^T [D,LK] fp16
__device__ __half g_Ph[(size_t)B_ * LQ_ * LK_];  // probs hi
__device__ __half g_Pl[(size_t)B_ * LQ_ * LK_];  // probs lo
__device__ float  g_S[(size_t)B_ * LQ_ * LK_];   // fp32 logits

// ---------------------------------------------------------------------------
// Helpers (base sm_103 ISA: cp.async + ldmatrix + mma.sync)
// ---------------------------------------------------------------------------
__device__ __forceinline__ uint32_t smem_u32(const void* p) {
    uint32_t a;
    asm("{ .reg .u64 t; cvta.to.shared.u64 t, %1; cvt.u32.u64 %0, t; }" : "=r"(a) : "l"(p));
    return a;
}

__device__ __forceinline__ void cp16(uint32_t saddr, const void* gaddr) {
    asm volatile("cp.async.cg.shared.global [%0], [%1], 16;\n" :: "r"(saddr), "l"(gaddr));
}

__device__ __forceinline__ void ldsm4(uint32_t* r, uint32_t addr) {
    asm volatile("ldmatrix.sync.aligned.m8n8.x4.shared.b16 {%0,%1,%2,%3}, [%4];"
                 : "=r"(r[0]), "=r"(r[1]), "=r"(r[2]), "=r"(r[3]) : "r"(addr));
}

// main term: fp16 inputs, fp32 accumulate (rt ~8)
__device__ __forceinline__ void mma_f32acc(float* c, const uint32_t* a, const uint32_t* b) {
    asm volatile("mma.sync.aligned.m16n8k16.row.col.f32.f16.f16.f32 "
                 "{%0,%1,%2,%3}, {%4,%5,%6,%7}, {%8,%9}, {%0,%1,%2,%3};"
                 : "+f"(c[0]), "+f"(c[1]), "+f"(c[2]), "+f"(c[3])
                 : "r"(a[0]), "r"(a[1]), "r"(a[2]), "r"(a[3]), "r"(b[0]), "r"(b[1]));
}

// cross term: fp16 inputs, fp16 accumulate (rt ~4). Term is ~2^-11 of total,
// so fp16 accumulation error (~2^-11 of the term) is ~2^-20 of total.
__device__ __forceinline__ void mma_f16acc(uint32_t* c, const uint32_t* a, const uint32_t* b) {
    asm volatile("mma.sync.aligned.m16n8k16.row.col.f16.f16.f16.f16 "
                 "{%0,%1}, {%2,%3,%4,%5}, {%6,%7}, {%0,%1};"
                 : "+r"(c[0]), "+r"(c[1])
                 : "r"(a[0]), "r"(a[1]), "r"(a[2]), "r"(a[3]), "r"(b[0]), "r"(b[1]));
}

__device__ __forceinline__ void split2h(float v, __half& h, __half& l) {
    h = __float2half(v);
    l = __float2half(v - __half2float(h));
}

// ---------------------------------------------------------------------------
// Conversion passes
// ---------------------------------------------------------------------------
__global__ __launch_bounds__(256) void qconv_kernel(const float* __restrict__ in,
                                                    const float* __restrict__ sc) {
    size_t i = ((size_t)blockIdx.x * 256 + threadIdx.x) * 8;
    float4 a = *(const float4*)(in + i);
    float4 b = *(const float4*)(in + i + 4);
    float4 s0 = *(const float4*)(sc + (i & (D_ - 1)));
    float4 s1 = *(const float4*)(sc + ((i + 4) & (D_ - 1)));
    float v[8] = {a.x * s0.x, a.y * s0.y, a.z * s0.z, a.w * s0.w,
                  b.x * s1.x, b.y * s1.y, b.z * s1.z, b.w * s1.w};
    __half h[8], l[8];
#pragma unroll
    for (int j = 0; j < 8; j++) split2h(v[j], h[j], l[j]);
    *(uint4*)(g_Qh + i) = *(uint4*)h;
    *(uint4*)(g_Ql + i) = *(uint4*)l;
}

// memory [LK,D] fp32 -> g_Mh [LK,D] fp16 AND g_MTh [D,LK] fp16, 32x32 tiles
__global__ __launch_bounds__(256) void mconv_kernel(const float* __restrict__ mem) {
    __shared__ float tile[32][33];
    const int d0 = blockIdx.x * 32;
    const int k0 = blockIdx.y * 32;
    const int bz = blockIdx.z;
    const int tx = threadIdx.x & 31;
    const int ty = threadIdx.x >> 5;  // 0..7
    const float* src = mem + (size_t)bz * LK_ * D_;
#pragma unroll
    for (int j = 0; j < 4; j++) {
        int kl = ty + j * 8;
        float v = src[(size_t)(k0 + kl) * D_ + d0 + tx];
        tile[kl][tx] = v;
        g_Mh[(size_t)bz * LK_ * D_ + (size_t)(k0 + kl) * D_ + d0 + tx] = __float2half(v);
    }
    __syncthreads();
#pragma unroll
    for (int j = 0; j < 4; j++) {
        int dl = ty + j * 8;
        float v = tile[tx][dl];
        g_MTh[(size_t)bz * D_ * LK_ + (size_t)(d0 + dl) * LK_ + k0 + tx] = __float2half(v);
    }
}

// ---------------------------------------------------------------------------
// Mixed-precision fp16 warp-MMA GEMM:
//   D ~= Ah@B^T (f32 acc)  +  Al@B^T (f16 acc)
//   CTA tile 128(M) x 256(N), 512 threads = 16 warps, warp tile 32x64.
//   K-chunk 64, 3 smem stages (216KB).
// Rows padded to 144B: r*144 mod 128 cycles all 8 16B banks over 8 rows
// -> conflict-free ldmatrix without XOR swizzle.
// ---------------------------------------------------------------------------
#define ROWB  144
#define STG_A (128 * ROWB)                        // 18432 (per A array)
#define STG_B (256 * ROWB)                        // 36864
#define STAGE_BYTES (2 * STG_A + STG_B)           // 73728
#define NSTAGE 3
#define GEMM_SMEM (NSTAGE * STAGE_BYTES)          // 221184

template <bool QK>
__global__ __launch_bounds__(512, 1) void gemm_kernel(const float* __restrict__ mask,
                                                      float* __restrict__ outp) {
    constexpr int KDIM = QK ? D_ : LK_;      // contraction length
    constexpr int NDIM = QK ? LK_ : D_;      // output columns / B rows
    constexpr int NC   = KDIM / 64;          // K chunks

    extern __shared__ char smem_raw[];
    const uint32_t sb = smem_u32(smem_raw);

    const int t  = threadIdx.x;
    const int b  = blockIdx.z;
    const int m0 = blockIdx.y * 128;
    const int n0 = blockIdx.x * 256;

    const __half* Ah = (QK ? g_Qh : g_Ph)  + ((size_t)b * LQ_  + m0) * KDIM;
    const __half* Al = (QK ? g_Ql : g_Pl)  + ((size_t)b * LQ_  + m0) * KDIM;
    const __half* Bp = (QK ? g_Mh : g_MTh) + ((size_t)b * NDIM + n0) * KDIM;

    float    acc[2][8][4];      // main, fp32
    uint32_t xac[2][8][2];      // cross, fp16x2
#pragma unroll
    for (int i = 0; i < 2; i++)
#pragma unroll
        for (int j = 0; j < 8; j++) {
#pragma unroll
            for (int k = 0; k < 4; k++) acc[i][j][k] = 0.0f;
            xac[i][j][0] = 0u; xac[i][j][1] = 0u;
        }

    // ---- async loader: chunk c -> stage c%3, 64 k-elems = 8 x 16B per row ----
    auto load_chunk = [&](int c) {
        const uint32_t st = sb + (c % NSTAGE) * STAGE_BYTES;
        const int koff = c * 64;
#pragma unroll
        for (int i = 0; i < 2; i++) {          // A hi+lo: 128 rows x 8 chunks
            int id  = t + (i << 9);
            int row = id >> 3, ch = id & 7;
            uint32_t so = (uint32_t)(row * ROWB + ch * 16);
            size_t   go = (size_t)row * KDIM + koff + ch * 8;
            cp16(st + so,         Ah + go);
            cp16(st + STG_A + so, Al + go);
        }
#pragma unroll
        for (int i = 0; i < 4; i++) {          // B: 256 rows x 8 chunks
            int id  = t + (i << 9);
            int row = id >> 3, ch = id & 7;
            uint32_t so = (uint32_t)(row * ROWB + ch * 16);
            size_t   go = (size_t)row * KDIM + koff + ch * 8;
            cp16(st + 2 * STG_A + so, Bp + go);
        }
        asm volatile("cp.async.commit_group;\n" ::: "memory");
    };

    const int lane = t & 31;
    const int w    = t >> 5;           // 0..15
    const int wm   = (w >> 2) * 32;    // warp M origin (4 x 32)
    const int wn   = (w & 3) * 64;     // warp N origin (4 x 64)

    const int a_row   = wm + (lane & 15);
    const int a_khalf = lane >> 4;                       // 0/1 -> k+0 / k+8
    const int b_row   = wn + (lane & 7) + ((lane >> 4) << 3);
    const int b_khalf = (lane >> 3) & 1;

    load_chunk(0);
    load_chunk(1);
    load_chunk(2);

    for (int c = 0; c < NC; c++) {
        const int rem = NC - 1 - c;
        if (rem >= 2)      asm volatile("cp.async.wait_group 2;\n" ::: "memory");
        else if (rem == 1) asm volatile("cp.async.wait_group 1;\n" ::: "memory");
        else               asm volatile("cp.async.wait_group 0;\n" ::: "memory");
        __syncthreads();

        const uint32_t st   = sb + (c % NSTAGE) * STAGE_BYTES;
        const uint32_t stAh = st;
        const uint32_t stAl = st + STG_A;
        const uint32_t stB  = st + 2 * STG_A;

#pragma unroll
        for (int k16 = 0; k16 < 4; k16++) {
            uint32_t ah[2][4], al[2][4], bf[4][4];
            const uint32_t a_off = (uint32_t)(a_row * ROWB + k16 * 32 + a_khalf * 16);
            const uint32_t b_off = (uint32_t)(b_row * ROWB + k16 * 32 + b_khalf * 16);
#pragma unroll
            for (int j = 0; j < 4; j++) ldsm4(bf[j], stB + b_off + j * (16 * ROWB));
#pragma unroll
            for (int i = 0; i < 2; i++) ldsm4(ah[i], stAh + a_off + i * (16 * ROWB));

            // main: Ah * B (fp32 acc)
#pragma unroll
            for (int i = 0; i < 2; i++)
#pragma unroll
                for (int jj = 0; jj < 8; jj++)
                    mma_f32acc(acc[i][jj], ah[i], &bf[jj >> 1][(jj & 1) * 2]);

#pragma unroll
            for (int i = 0; i < 2; i++) ldsm4(al[i], stAl + a_off + i * (16 * ROWB));

            // cross: Al * B (fp16 acc)
#pragma unroll
            for (int i = 0; i < 2; i++)
#pragma unroll
                for (int jj = 0; jj < 8; jj++)
                    mma_f16acc(xac[i][jj], al[i], &bf[jj >> 1][(jj & 1) * 2]);
        }

        __syncthreads();                    // all warps done before stage reuse
        if (c + NSTAGE < NC) load_chunk(c + NSTAGE);
    }

    // ---- epilogue: out = main + cross ----
    float* Cbase = QK ? (g_S + (size_t)b * LQ_ * LK_) : (outp + (size_t)b * LQ_ * D_);
    const float* mrow = QK ? (mask + (size_t)b * LK_) : nullptr;

#pragma unroll
    for (int i = 0; i < 2; i++) {
        const int r0 = m0 + wm + i * 16 + (lane >> 2);
#pragma unroll
        for (int jj = 0; jj < 8; jj++) {
            const int col = n0 + wn + jj * 8 + (lane & 3) * 2;
            float2 xlo = __half22float2(*(const __half2*)&xac[i][jj][0]);
            float2 xhi = __half22float2(*(const __half2*)&xac[i][jj][1]);
            float v0 = acc[i][jj][0] + xlo.x;
            float v1 = acc[i][jj][1] + xlo.y;
            float v2 = acc[i][jj][2] + xhi.x;
            float v3 = acc[i][jj][3] + xhi.y;
            if (QK) {
                const float mk0 = 1e30f * __ldg(mrow + col);
                const float mk1 = 1e30f * __ldg(mrow + col + 1);
                v0 -= mk0; v1 -= mk1; v2 -= mk0; v3 -= mk1;
            }
            *(float2*)(Cbase + (size_t)r0 * NDIM + col)       = make_float2(v0, v1);
            *(float2*)(Cbase + (size_t)(r0 + 8) * NDIM + col) = make_float2(v2, v3);
        }
    }
}

// ---------------------------------------------------------------------------
// Softmax: fp32 logits row -> fp16 hi/lo probability row
// ---------------------------------------------------------------------------
__global__ __launch_bounds__(256) void softmax_kernel() {
    const float* p = g_S + (size_t)blockIdx.x * LK_;
    const int tid = threadIdx.x;

    float4 a = *(const float4*)(p + tid * 8);
    float4 c = *(const float4*)(p + tid * 8 + 4);

    float m = fmaxf(fmaxf(fmaxf(a.x, a.y), fmaxf(a.z, a.w)),
                    fmaxf(fmaxf(c.x, c.y), fmaxf(c.z, c.w)));
#pragma unroll
    for (int o = 16; o > 0; o >>= 1) m = fmaxf(m, __shfl_xor_sync(0xffffffffu, m, o));

    __shared__ float red[8];
    const int warp = tid >> 5;
    if ((tid & 31) == 0) red[warp] = m;
    __syncthreads();
    m = red[0];
#pragma unroll
    for (int i = 1; i < 8; i++) m = fmaxf(m, red[i]);

    a.x = expf(a.x - m); a.y = expf(a.y - m); a.z = expf(a.z - m); a.w = expf(a.w - m);
    c.x = expf(c.x - m); c.y = expf(c.y - m); c.z = expf(c.z - m); c.w = expf(c.w - m);

    float s = (a.x + a.y) + (a.z + a.w) + (c.x + c.y) + (c.z + c.w);
#pragma unroll
    for (int o = 16; o > 0; o >>= 1) s += __shfl_xor_sync(0xffffffffu, s, o);

    __syncthreads();
    if ((tid & 31) == 0) red[warp] = s;
    __syncthreads();
    s = ((red[0] + red[1]) + (red[2] + red[3])) + ((red[4] + red[5]) + (red[6] + red[7]));

    const float inv = 1.0f / s;
    float v[8] = {a.x * inv, a.y * inv, a.z * inv, a.w * inv,
                  c.x * inv, c.y * inv, c.z * inv, c.w * inv};
    __half h[8], l[8];
#pragma unroll
    for (int j = 0; j < 8; j++) split2h(v[j], h[j], l[j]);
    size_t base = (size_t)blockIdx.x * LK_ + tid * 8;
    *(uint4*)(g_Ph + base) = *(uint4*)h;
    *(uint4*)(g_Pl + base) = *(uint4*)l;
}

// ---------------------------------------------------------------------------
// inputs: 0=input 1=memory 2=mask 3=w_input (cancels in softmax) 4=dot_scale
// ---------------------------------------------------------------------------
extern "C" void kernel_launch(void* const* d_in, const int* in_sizes, int n_in,
                              void* d_out, int out_size) {
    const float* input     = (const float*)d_in[0];
    const float* memory    = (const float*)d_in[1];
    const float* mask      = (const float*)d_in[2];
    const float* dot_scale = (const float*)d_in[4];
    float* out = (float*)d_out;

    cudaFuncSetAttribute(gemm_kernel<true>,  cudaFuncAttributeMaxDynamicSharedMemorySize, GEMM_SMEM);
    cudaFuncSetAttribute(gemm_kernel<false>, cudaFuncAttributeMaxDynamicSharedMemorySize, GEMM_SMEM);

    qconv_kernel<<<(size_t)B_ * LQ_ * D_ / 2048, 256>>>(input, dot_scale);
    mconv_kernel<<<dim3(D_ / 32, LK_ / 32, B_), 256>>>(memory);

    gemm_kernel<true><<<dim3(LK_ / 256, LQ_ / 128, B_), 512, GEMM_SMEM>>>(mask, nullptr);

    softmax_kernel<<<B_ * LQ_, 256>>>();

    gemm_kernel<false><<<dim3(D_ / 256, LQ_ / 128, B_), 512, GEMM_SMEM>>>(nullptr, out);
}

// round 6
// speedup vs baseline: 4.4791x; 1.5878x over previous
#include <cuda_runtime.h>
#include <cuda_fp16.h>
#include <cstdint>

#define B_  8
#define LQ_ 2048
#define LK_ 2048
#define D_  1024

// ---------------------------------------------------------------------------
// Static device scratch (no runtime allocation allowed)
// ---------------------------------------------------------------------------
__device__ __half g_Qh[(size_t)B_ * LQ_ * D_];   // (input*scale) fp16
__device__ __half g_Mh[(size_t)B_ * LK_ * D_];   // memory [LK,D] fp16
__device__ __half g_MTh[(size_t)B_ * D_ * LK_];  // memory^T [D,LK] fp16
__device__ __half g_Ph[(size_t)B_ * LQ_ * LK_];  // probs fp16
__device__ float  g_S[(size_t)B_ * LQ_ * LK_];   // fp32 logits

// ---------------------------------------------------------------------------
// Helpers (base sm_103 ISA: cp.async + ldmatrix + mma.sync)
// ---------------------------------------------------------------------------
__device__ __forceinline__ uint32_t smem_u32(const void* p) {
    uint32_t a;
    asm("{ .reg .u64 t; cvta.to.shared.u64 t, %1; cvt.u32.u64 %0, t; }" : "=r"(a) : "l"(p));
    return a;
}

__device__ __forceinline__ void cp16(uint32_t saddr, const void* gaddr) {
    asm volatile("cp.async.cg.shared.global [%0], [%1], 16;\n" :: "r"(saddr), "l"(gaddr));
}

__device__ __forceinline__ void ldsm4(uint32_t* r, uint32_t addr) {
    asm volatile("ldmatrix.sync.aligned.m8n8.x4.shared.b16 {%0,%1,%2,%3}, [%4];"
                 : "=r"(r[0]), "=r"(r[1]), "=r"(r[2]), "=r"(r[3]) : "r"(addr));
}

__device__ __forceinline__ void mma_f32acc(float* c, const uint32_t* a, const uint32_t* b) {
    asm volatile("mma.sync.aligned.m16n8k16.row.col.f32.f16.f16.f32 "
                 "{%0,%1,%2,%3}, {%4,%5,%6,%7}, {%8,%9}, {%0,%1,%2,%3};"
                 : "+f"(c[0]), "+f"(c[1]), "+f"(c[2]), "+f"(c[3])
                 : "r"(a[0]), "r"(a[1]), "r"(a[2]), "r"(a[3]), "r"(b[0]), "r"(b[1]));
}

// ---------------------------------------------------------------------------
// Conversion passes
// ---------------------------------------------------------------------------
__global__ __launch_bounds__(256) void qconv_kernel(const float* __restrict__ in,
                                                    const float* __restrict__ sc) {
    size_t i = ((size_t)blockIdx.x * 256 + threadIdx.x) * 8;
    float4 a = *(const float4*)(in + i);
    float4 b = *(const float4*)(in + i + 4);
    float4 s0 = *(const float4*)(sc + (i & (D_ - 1)));
    float4 s1 = *(const float4*)(sc + ((i + 4) & (D_ - 1)));
    __half h[8] = {__float2half(a.x * s0.x), __float2half(a.y * s0.y),
                   __float2half(a.z * s0.z), __float2half(a.w * s0.w),
                   __float2half(b.x * s1.x), __float2half(b.y * s1.y),
                   __float2half(b.z * s1.z), __float2half(b.w * s1.w)};
    *(uint4*)(g_Qh + i) = *(uint4*)h;
}

// memory [LK,D] fp32 -> g_Mh [LK,D] fp16 AND g_MTh [D,LK] fp16, 32x32 tiles
__global__ __launch_bounds__(256) void mconv_kernel(const float* __restrict__ mem) {
    __shared__ float tile[32][33];
    const int d0 = blockIdx.x * 32;
    const int k0 = blockIdx.y * 32;
    const int bz = blockIdx.z;
    const int tx = threadIdx.x & 31;
    const int ty = threadIdx.x >> 5;  // 0..7
    const float* src = mem + (size_t)bz * LK_ * D_;
#pragma unroll
    for (int j = 0; j < 4; j++) {
        int kl = ty + j * 8;
        float v = src[(size_t)(k0 + kl) * D_ + d0 + tx];
        tile[kl][tx] = v;
        g_Mh[(size_t)bz * LK_ * D_ + (size_t)(k0 + kl) * D_ + d0 + tx] = __float2half(v);
    }
    __syncthreads();
#pragma unroll
    for (int j = 0; j < 4; j++) {
        int dl = ty + j * 8;
        g_MTh[(size_t)bz * D_ * LK_ + (size_t)(d0 + dl) * LK_ + k0 + tx] =
            __float2half(tile[tx][dl]);
    }
}

// ---------------------------------------------------------------------------
// fp16 warp-MMA GEMM (single term, fp32 accumulate):
//   CTA tile 128(M) x 256(N), 512 threads = 16 warps, warp tile 32x64.
//   K-chunk 64, 4 smem stages (216KB).
// Rows padded to 144B: r*144 mod 128 cycles all 8 16B banks over 8 rows
// -> conflict-free ldmatrix without XOR swizzle.
// ---------------------------------------------------------------------------
#define ROWB  144
#define STG_A (128 * ROWB)                        // 18432
#define STG_B (256 * ROWB)                        // 36864
#define STAGE_BYTES (STG_A + STG_B)               // 55296
#define NSTAGE 4
#define GEMM_SMEM (NSTAGE * STAGE_BYTES)          // 221184

template <bool QK>
__global__ __launch_bounds__(512, 1) void gemm_kernel(const float* __restrict__ mask,
                                                      float* __restrict__ outp) {
    constexpr int KDIM = QK ? D_ : LK_;      // contraction length
    constexpr int NDIM = QK ? LK_ : D_;      // output columns / B rows
    constexpr int NC   = KDIM / 64;          // K chunks

    extern __shared__ char smem_raw[];
    const uint32_t sb = smem_u32(smem_raw);

    const int t  = threadIdx.x;
    const int b  = blockIdx.z;
    const int m0 = blockIdx.y * 128;
    const int n0 = blockIdx.x * 256;

    const __half* Ap = (QK ? g_Qh : g_Ph)  + ((size_t)b * LQ_  + m0) * KDIM;
    const __half* Bp = (QK ? g_Mh : g_MTh) + ((size_t)b * NDIM + n0) * KDIM;

    float acc[2][8][4];
#pragma unroll
    for (int i = 0; i < 2; i++)
#pragma unroll
        for (int j = 0; j < 8; j++)
#pragma unroll
            for (int k = 0; k < 4; k++) acc[i][j][k] = 0.0f;

    // ---- async loader: chunk c -> stage c%4, 64 k-elems = 8 x 16B per row ----
    auto load_chunk = [&](int c) {
        const uint32_t st = sb + (c % NSTAGE) * STAGE_BYTES;
        const int koff = c * 64;
#pragma unroll
        for (int i = 0; i < 2; i++) {          // A: 128 rows x 8 chunks
            int id  = t + (i << 9);
            int row = id >> 3, ch = id & 7;
            uint32_t so = (uint32_t)(row * ROWB + ch * 16);
            cp16(st + so, Ap + (size_t)row * KDIM + koff + ch * 8);
        }
#pragma unroll
        for (int i = 0; i < 4; i++) {          // B: 256 rows x 8 chunks
            int id  = t + (i << 9);
            int row = id >> 3, ch = id & 7;
            uint32_t so = (uint32_t)(row * ROWB + ch * 16);
            cp16(st + STG_A + so, Bp + (size_t)row * KDIM + koff + ch * 8);
        }
        asm volatile("cp.async.commit_group;\n" ::: "memory");
    };

    const int lane = t & 31;
    const int w    = t >> 5;           // 0..15
    const int wm   = (w >> 2) * 32;    // warp M origin (4 x 32)
    const int wn   = (w & 3) * 64;     // warp N origin (4 x 64)

    const int a_row   = wm + (lane & 15);
    const int a_khalf = lane >> 4;                       // 0/1 -> k+0 / k+8
    const int b_row   = wn + (lane & 7) + ((lane >> 4) << 3);
    const int b_khalf = (lane >> 3) & 1;

    load_chunk(0);
    load_chunk(1);
    load_chunk(2);
    load_chunk(3);

    for (int c = 0; c < NC; c++) {
        const int rem = NC - 1 - c;
        if (rem >= 3)      asm volatile("cp.async.wait_group 3;\n" ::: "memory");
        else if (rem == 2) asm volatile("cp.async.wait_group 2;\n" ::: "memory");
        else if (rem == 1) asm volatile("cp.async.wait_group 1;\n" ::: "memory");
        else               asm volatile("cp.async.wait_group 0;\n" ::: "memory");
        __syncthreads();

        const uint32_t stA = sb + (c % NSTAGE) * STAGE_BYTES;
        const uint32_t stB = stA + STG_A;

#pragma unroll
        for (int k16 = 0; k16 < 4; k16++) {
            uint32_t af[2][4], bf[4][4];
            const uint32_t a_off = (uint32_t)(a_row * ROWB + k16 * 32 + a_khalf * 16);
            const uint32_t b_off = (uint32_t)(b_row * ROWB + k16 * 32 + b_khalf * 16);
#pragma unroll
            for (int j = 0; j < 4; j++) ldsm4(bf[j], stB + b_off + j * (16 * ROWB));
#pragma unroll
            for (int i = 0; i < 2; i++) ldsm4(af[i], stA + a_off + i * (16 * ROWB));
#pragma unroll
            for (int i = 0; i < 2; i++)
#pragma unroll
                for (int jj = 0; jj < 8; jj++)
                    mma_f32acc(acc[i][jj], af[i], &bf[jj >> 1][(jj & 1) * 2]);
        }

        __syncthreads();                    // all warps done before stage reuse
        if (c + NSTAGE < NC) load_chunk(c + NSTAGE);
    }

    // ---- epilogue ----
    float* Cbase = QK ? (g_S + (size_t)b * LQ_ * LK_) : (outp + (size_t)b * LQ_ * D_);
    const float* mrow = QK ? (mask + (size_t)b * LK_) : nullptr;

#pragma unroll
    for (int i = 0; i < 2; i++) {
        const int r0 = m0 + wm + i * 16 + (lane >> 2);
#pragma unroll
        for (int jj = 0; jj < 8; jj++) {
            const int col = n0 + wn + jj * 8 + (lane & 3) * 2;
            float v0 = acc[i][jj][0], v1 = acc[i][jj][1];
            float v2 = acc[i][jj][2], v3 = acc[i][jj][3];
            if (QK) {
                const float mk0 = 1e30f * __ldg(mrow + col);
                const float mk1 = 1e30f * __ldg(mrow + col + 1);
                v0 -= mk0; v1 -= mk1; v2 -= mk0; v3 -= mk1;
            }
            *(float2*)(Cbase + (size_t)r0 * NDIM + col)       = make_float2(v0, v1);
            *(float2*)(Cbase + (size_t)(r0 + 8) * NDIM + col) = make_float2(v2, v3);
        }
    }
}

// ---------------------------------------------------------------------------
// Softmax: fp32 logits row -> fp16 probability row
// ---------------------------------------------------------------------------
__global__ __launch_bounds__(256) void softmax_kernel() {
    const float* p = g_S + (size_t)blockIdx.x * LK_;
    const int tid = threadIdx.x;

    float4 a = *(const float4*)(p + tid * 8);
    float4 c = *(const float4*)(p + tid * 8 + 4);

    float m = fmaxf(fmaxf(fmaxf(a.x, a.y), fmaxf(a.z, a.w)),
                    fmaxf(fmaxf(c.x, c.y), fmaxf(c.z, c.w)));
#pragma unroll
    for (int o = 16; o > 0; o >>= 1) m = fmaxf(m, __shfl_xor_sync(0xffffffffu, m, o));

    __shared__ float red[8];
    const int warp = tid >> 5;
    if ((tid & 31) == 0) red[warp] = m;
    __syncthreads();
    m = red[0];
#pragma unroll
    for (int i = 1; i < 8; i++) m = fmaxf(m, red[i]);

    a.x = expf(a.x - m); a.y = expf(a.y - m); a.z = expf(a.z - m); a.w = expf(a.w - m);
    c.x = expf(c.x - m); c.y = expf(c.y - m); c.z = expf(c.z - m); c.w = expf(c.w - m);

    float s = (a.x + a.y) + (a.z + a.w) + (c.x + c.y) + (c.z + c.w);
#pragma unroll
    for (int o = 16; o > 0; o >>= 1) s += __shfl_xor_sync(0xffffffffu, s, o);

    __syncthreads();
    if ((tid & 31) == 0) red[warp] = s;
    __syncthreads();
    s = ((red[0] + red[1]) + (red[2] + red[3])) + ((red[4] + red[5]) + (red[6] + red[7]));

    const float inv = 1.0f / s;
    __half h[8] = {__float2half(a.x * inv), __float2half(a.y * inv),
                   __float2half(a.z * inv), __float2half(a.w * inv),
                   __float2half(c.x * inv), __float2half(c.y * inv),
                   __float2half(c.z * inv), __float2half(c.w * inv)};
    *(uint4*)(g_Ph + (size_t)blockIdx.x * LK_ + tid * 8) = *(uint4*)h;
}

// ---------------------------------------------------------------------------
// inputs: 0=input 1=memory 2=mask 3=w_input (cancels in softmax) 4=dot_scale
// ---------------------------------------------------------------------------
extern "C" void kernel_launch(void* const* d_in, const int* in_sizes, int n_in,
                              void* d_out, int out_size) {
    const float* input     = (const float*)d_in[0];
    const float* memory    = (const float*)d_in[1];
    const float* mask      = (const float*)d_in[2];
    const float* dot_scale = (const float*)d_in[4];
    float* out = (float*)d_out;

    cudaFuncSetAttribute(gemm_kernel<true>,  cudaFuncAttributeMaxDynamicSharedMemorySize, GEMM_SMEM);
    cudaFuncSetAttribute(gemm_kernel<false>, cudaFuncAttributeMaxDynamicSharedMemorySize, GEMM_SMEM);

    qconv_kernel<<<(size_t)B_ * LQ_ * D_ / 2048, 256>>>(input, dot_scale);
    mconv_kernel<<<dim3(D_ / 32, LK_ / 32, B_), 256>>>(memory);

    gemm_kernel<true><<<dim3(LK_ / 256, LQ_ / 128, B_), 512, GEMM_SMEM>>>(mask, nullptr);

    softmax_kernel<<<B_ * LQ_, 256>>>();

    gemm_kernel<false><<<dim3(D_ / 256, LQ_ / 128, B_), 512, GEMM_SMEM>>>(nullptr, out);
}

// round 7
// speedup vs baseline: 4.7704x; 1.0650x over previous
#include <cuda_runtime.h>
#include <cuda_fp16.h>
#include <cstdint>

#define B_  8
#define LQ_ 2048
#define LK_ 2048
#define D_  1024

// ---------------------------------------------------------------------------
// Static device scratch (no runtime allocation allowed)
// ---------------------------------------------------------------------------
__device__ __half g_Qh[(size_t)B_ * LQ_ * D_];   // (input*scale) fp16
__device__ __half g_Mh[(size_t)B_ * LK_ * D_];   // memory [LK,D] fp16
__device__ __half g_MTh[(size_t)B_ * D_ * LK_];  // memory^T [D,LK] fp16
__device__ __half g_Ph[(size_t)B_ * LQ_ * LK_];  // probs fp16
__device__ __half g_Sh[(size_t)B_ * LQ_ * LK_];  // fp16 logits (mask NOT applied)

// ---------------------------------------------------------------------------
// Helpers (base sm_103 ISA: cp.async + ldmatrix + mma.sync)
// ---------------------------------------------------------------------------
__device__ __forceinline__ uint32_t smem_u32(const void* p) {
    uint32_t a;
    asm("{ .reg .u64 t; cvta.to.shared.u64 t, %1; cvt.u32.u64 %0, t; }" : "=r"(a) : "l"(p));
    return a;
}

__device__ __forceinline__ void cp16(uint32_t saddr, const void* gaddr) {
    asm volatile("cp.async.cg.shared.global [%0], [%1], 16;\n" :: "r"(saddr), "l"(gaddr));
}

__device__ __forceinline__ void ldsm4(uint32_t* r, uint32_t addr) {
    asm volatile("ldmatrix.sync.aligned.m8n8.x4.shared.b16 {%0,%1,%2,%3}, [%4];"
                 : "=r"(r[0]), "=r"(r[1]), "=r"(r[2]), "=r"(r[3]) : "r"(addr));
}

__device__ __forceinline__ void mma_f32acc(float* c, const uint32_t* a, const uint32_t* b) {
    asm volatile("mma.sync.aligned.m16n8k16.row.col.f32.f16.f16.f32 "
                 "{%0,%1,%2,%3}, {%4,%5,%6,%7}, {%8,%9}, {%0,%1,%2,%3};"
                 : "+f"(c[0]), "+f"(c[1]), "+f"(c[2]), "+f"(c[3])
                 : "r"(a[0]), "r"(a[1]), "r"(a[2]), "r"(a[3]), "r"(b[0]), "r"(b[1]));
}

// ---------------------------------------------------------------------------
// Conversion passes
// ---------------------------------------------------------------------------
__global__ __launch_bounds__(256) void qconv_kernel(const float* __restrict__ in,
                                                    const float* __restrict__ sc) {
    size_t i = ((size_t)blockIdx.x * 256 + threadIdx.x) * 8;
    float4 a = *(const float4*)(in + i);
    float4 b = *(const float4*)(in + i + 4);
    float4 s0 = *(const float4*)(sc + (i & (D_ - 1)));
    float4 s1 = *(const float4*)(sc + ((i + 4) & (D_ - 1)));
    __half h[8] = {__float2half(a.x * s0.x), __float2half(a.y * s0.y),
                   __float2half(a.z * s0.z), __float2half(a.w * s0.w),
                   __float2half(b.x * s1.x), __float2half(b.y * s1.y),
                   __float2half(b.z * s1.z), __float2half(b.w * s1.w)};
    *(uint4*)(g_Qh + i) = *(uint4*)h;
}

// memory [LK,D] fp32 -> g_Mh [LK,D] fp16 AND g_MTh [D,LK] fp16, 32x32 tiles
__global__ __launch_bounds__(256) void mconv_kernel(const float* __restrict__ mem) {
    __shared__ float tile[32][33];
    const int d0 = blockIdx.x * 32;
    const int k0 = blockIdx.y * 32;
    const int bz = blockIdx.z;
    const int tx = threadIdx.x & 31;
    const int ty = threadIdx.x >> 5;  // 0..7
    const float* src = mem + (size_t)bz * LK_ * D_;
#pragma unroll
    for (int j = 0; j < 4; j++) {
        int kl = ty + j * 8;
        float v = src[(size_t)(k0 + kl) * D_ + d0 + tx];
        tile[kl][tx] = v;
        g_Mh[(size_t)bz * LK_ * D_ + (size_t)(k0 + kl) * D_ + d0 + tx] = __float2half(v);
    }
    __syncthreads();
#pragma unroll
    for (int j = 0; j < 4; j++) {
        int dl = ty + j * 8;
        g_MTh[(size_t)bz * D_ * LK_ + (size_t)(d0 + dl) * LK_ + k0 + tx] =
            __float2half(tile[tx][dl]);
    }
}

// ---------------------------------------------------------------------------
// fp16 warp-MMA GEMM (fp32 accumulate):
//   CTA tile 128(M) x 256(N), 512 threads = 16 warps, warp tile 32x64.
//   K-chunk 64, 4 smem stages, ONE barrier per mainloop iteration.
// Rows padded to 144B: r*144 mod 128 cycles all 8 16B banks over 8 rows
// -> conflict-free ldmatrix without XOR swizzle.
// ---------------------------------------------------------------------------
#define ROWB  144
#define STG_A (128 * ROWB)                        // 18432
#define STG_B (256 * ROWB)                        // 36864
#define STAGE_BYTES (STG_A + STG_B)               // 55296
#define NSTAGE 4
#define GEMM_SMEM (NSTAGE * STAGE_BYTES)          // 221184

template <bool QK>
__global__ __launch_bounds__(512, 1) void gemm_kernel(float* __restrict__ outp) {
    constexpr int KDIM = QK ? D_ : LK_;      // contraction length
    constexpr int NDIM = QK ? LK_ : D_;      // output columns / B rows
    constexpr int NC   = KDIM / 64;          // K chunks

    extern __shared__ char smem_raw[];
    const uint32_t sb = smem_u32(smem_raw);

    const int t  = threadIdx.x;
    const int b  = blockIdx.z;
    const int m0 = blockIdx.y * 128;
    const int n0 = blockIdx.x * 256;

    const __half* Ap = (QK ? g_Qh : g_Ph)  + ((size_t)b * LQ_  + m0) * KDIM;
    const __half* Bp = (QK ? g_Mh : g_MTh) + ((size_t)b * NDIM + n0) * KDIM;

    float acc[2][8][4];
#pragma unroll
    for (int i = 0; i < 2; i++)
#pragma unroll
        for (int j = 0; j < 8; j++)
#pragma unroll
            for (int k = 0; k < 4; k++) acc[i][j][k] = 0.0f;

    // ---- async loader: chunk c -> stage c%4, 64 k-elems = 8 x 16B per row ----
    auto load_chunk = [&](int c) {
        const uint32_t st = sb + (c % NSTAGE) * STAGE_BYTES;
        const int koff = c * 64;
#pragma unroll
        for (int i = 0; i < 2; i++) {          // A: 128 rows x 8 chunks
            int id  = t + (i << 9);
            int row = id >> 3, ch = id & 7;
            uint32_t so = (uint32_t)(row * ROWB + ch * 16);
            cp16(st + so, Ap + (size_t)row * KDIM + koff + ch * 8);
        }
#pragma unroll
        for (int i = 0; i < 4; i++) {          // B: 256 rows x 8 chunks
            int id  = t + (i << 9);
            int row = id >> 3, ch = id & 7;
            uint32_t so = (uint32_t)(row * ROWB + ch * 16);
            cp16(st + STG_A + so, Bp + (size_t)row * KDIM + koff + ch * 8);
        }
        asm volatile("cp.async.commit_group;\n" ::: "memory");
    };

    const int lane = t & 31;
    const int w    = t >> 5;           // 0..15
    const int wm   = (w >> 2) * 32;    // warp M origin (4 x 32)
    const int wn   = (w & 3) * 64;     // warp N origin (4 x 64)

    const int a_row   = wm + (lane & 15);
    const int a_khalf = lane >> 4;                       // 0/1 -> k+0 / k+8
    const int b_row   = wn + (lane & 7) + ((lane >> 4) << 3);
    const int b_khalf = (lane >> 3) & 1;

    // prefill NSTAGE-1 stages; the 4th is loaded inside the loop
    load_chunk(0);
    load_chunk(1);
    load_chunk(2);

    for (int c = 0; c < NC; c++) {
        // need group c complete; pending groups after this point <= last_issued - c
        const int rem = NC - 1 - c;                 // chunks not yet computed
        if (rem >= 2)      asm volatile("cp.async.wait_group 2;\n" ::: "memory");
        else if (rem == 1) asm volatile("cp.async.wait_group 1;\n" ::: "memory");
        else               asm volatile("cp.async.wait_group 0;\n" ::: "memory");
        __syncthreads();   // single barrier: publishes stage c, proves stage c-1 consumed

        // refill the stage consumed last iteration
        if (c + NSTAGE - 1 < NC) load_chunk(c + NSTAGE - 1);

        const uint32_t stA = sb + (c % NSTAGE) * STAGE_BYTES;
        const uint32_t stB = stA + STG_A;

#pragma unroll
        for (int k16 = 0; k16 < 4; k16++) {
            uint32_t af[2][4], bf[4][4];
            const uint32_t a_off = (uint32_t)(a_row * ROWB + k16 * 32 + a_khalf * 16);
            const uint32_t b_off = (uint32_t)(b_row * ROWB + k16 * 32 + b_khalf * 16);
#pragma unroll
            for (int j = 0; j < 4; j++) ldsm4(bf[j], stB + b_off + j * (16 * ROWB));
#pragma unroll
            for (int i = 0; i < 2; i++) ldsm4(af[i], stA + a_off + i * (16 * ROWB));
#pragma unroll
            for (int i = 0; i < 2; i++)
#pragma unroll
                for (int jj = 0; jj < 8; jj++)
                    mma_f32acc(acc[i][jj], af[i], &bf[jj >> 1][(jj & 1) * 2]);
        }
    }

    // ---- epilogue ----
#pragma unroll
    for (int i = 0; i < 2; i++) {
        const int r0 = m0 + wm + i * 16 + (lane >> 2);
#pragma unroll
        for (int jj = 0; jj < 8; jj++) {
            const int col = n0 + wn + jj * 8 + (lane & 3) * 2;
            if (QK) {
                // fp16 logits, mask applied later in softmax
                __half* Crow = g_Sh + (size_t)b * LQ_ * LK_;
                *(__half2*)(Crow + (size_t)r0 * NDIM + col) =
                    __floats2half2_rn(acc[i][jj][0], acc[i][jj][1]);
                *(__half2*)(Crow + (size_t)(r0 + 8) * NDIM + col) =
                    __floats2half2_rn(acc[i][jj][2], acc[i][jj][3]);
            } else {
                float* Crow = outp + (size_t)b * LQ_ * D_;
                *(float2*)(Crow + (size_t)r0 * NDIM + col) =
                    make_float2(acc[i][jj][0], acc[i][jj][1]);
                *(float2*)(Crow + (size_t)(r0 + 8) * NDIM + col) =
                    make_float2(acc[i][jj][2], acc[i][jj][3]);
            }
        }
    }
}

// ---------------------------------------------------------------------------
// Softmax: fp16 logits + mask (L2-resident) -> fp16 probability row
// ---------------------------------------------------------------------------
__global__ __launch_bounds__(256) void softmax_kernel(const float* __restrict__ mask) {
    const size_t row = blockIdx.x;
    const __half* p = g_Sh + row * LK_;
    const float* mrow = mask + (row >> 11) * LK_;   // row/LQ_ = batch
    const int tid = threadIdx.x;

    uint4 raw = *(const uint4*)(p + tid * 8);
    const __half2* hp = (const __half2*)&raw;
    float v[8];
#pragma unroll
    for (int j = 0; j < 4; j++) {
        float2 f = __half22float2(hp[j]);
        v[2 * j] = f.x; v[2 * j + 1] = f.y;
    }
    float4 mk0 = *(const float4*)(mrow + tid * 8);
    float4 mk1 = *(const float4*)(mrow + tid * 8 + 4);
    v[0] -= 1e30f * mk0.x; v[1] -= 1e30f * mk0.y;
    v[2] -= 1e30f * mk0.z; v[3] -= 1e30f * mk0.w;
    v[4] -= 1e30f * mk1.x; v[5] -= 1e30f * mk1.y;
    v[6] -= 1e30f * mk1.z; v[7] -= 1e30f * mk1.w;

    float m = v[0];
#pragma unroll
    for (int j = 1; j < 8; j++) m = fmaxf(m, v[j]);
#pragma unroll
    for (int o = 16; o > 0; o >>= 1) m = fmaxf(m, __shfl_xor_sync(0xffffffffu, m, o));

    __shared__ float red[8];
    const int warp = tid >> 5;
    if ((tid & 31) == 0) red[warp] = m;
    __syncthreads();
    m = red[0];
#pragma unroll
    for (int i = 1; i < 8; i++) m = fmaxf(m, red[i]);

    float s = 0.0f;
#pragma unroll
    for (int j = 0; j < 8; j++) { v[j] = expf(v[j] - m); s += v[j]; }
#pragma unroll
    for (int o = 16; o > 0; o >>= 1) s += __shfl_xor_sync(0xffffffffu, s, o);

    __syncthreads();
    if ((tid & 31) == 0) red[warp] = s;
    __syncthreads();
    s = ((red[0] + red[1]) + (red[2] + red[3])) + ((red[4] + red[5]) + (red[6] + red[7]));

    const float inv = 1.0f / s;
    __half h[8];
#pragma unroll
    for (int j = 0; j < 8; j++) h[j] = __float2half(v[j] * inv);
    *(uint4*)(g_Ph + row * LK_ + tid * 8) = *(uint4*)h;
}

// ---------------------------------------------------------------------------
// inputs: 0=input 1=memory 2=mask 3=w_input (cancels in softmax) 4=dot_scale
// ---------------------------------------------------------------------------
extern "C" void kernel_launch(void* const* d_in, const int* in_sizes, int n_in,
                              void* d_out, int out_size) {
    const float* input     = (const float*)d_in[0];
    const float* memory    = (const float*)d_in[1];
    const float* mask      = (const float*)d_in[2];
    const float* dot_scale = (const float*)d_in[4];
    float* out = (float*)d_out;

    cudaFuncSetAttribute(gemm_kernel<true>,  cudaFuncAttributeMaxDynamicSharedMemorySize, GEMM_SMEM);
    cudaFuncSetAttribute(gemm_kernel<false>, cudaFuncAttributeMaxDynamicSharedMemorySize, GEMM_SMEM);

    qconv_kernel<<<(size_t)B_ * LQ_ * D_ / 2048, 256>>>(input, dot_scale);
    mconv_kernel<<<dim3(D_ / 32, LK_ / 32, B_), 256>>>(memory);

    gemm_kernel<true><<<dim3(LK_ / 256, LQ_ / 128, B_), 512, GEMM_SMEM>>>(nullptr);

    softmax_kernel<<<B_ * LQ_, 256>>>(mask);

    gemm_kernel<false><<<dim3(D_ / 256, LQ_ / 128, B_), 512, GEMM_SMEM>>>(out);
}

// round 8
// speedup vs baseline: 4.8005x; 1.0063x over previous
#include <cuda_runtime.h>
#include <cuda_fp16.h>
#include <cstdint>

#define B_  8
#define LQ_ 2048
#define LK_ 2048
#define D_  1024

// ---------------------------------------------------------------------------
// Static device scratch (no runtime allocation allowed)
// ---------------------------------------------------------------------------
__device__ __half g_Qh[(size_t)B_ * LQ_ * D_];   // (input*scale) fp16
__device__ __half g_Mh[(size_t)B_ * LK_ * D_];   // memory [LK,D] fp16
__device__ __half g_MTh[(size_t)B_ * D_ * LK_];  // memory^T [D,LK] fp16
__device__ __half g_Ph[(size_t)B_ * LQ_ * LK_];  // probs fp16
__device__ __half g_Sh[(size_t)B_ * LQ_ * LK_];  // fp16 logits (mask NOT applied)

// ---------------------------------------------------------------------------
// Helpers (base sm_103 ISA: cp.async + ldmatrix + mma.sync)
// ---------------------------------------------------------------------------
__device__ __forceinline__ uint32_t smem_u32(const void* p) {
    uint32_t a;
    asm("{ .reg .u64 t; cvta.to.shared.u64 t, %1; cvt.u32.u64 %0, t; }" : "=r"(a) : "l"(p));
    return a;
}

__device__ __forceinline__ void cp16(uint32_t saddr, const void* gaddr) {
    asm volatile("cp.async.cg.shared.global [%0], [%1], 16;\n" :: "r"(saddr), "l"(gaddr));
}

__device__ __forceinline__ void ldsm4(uint32_t* r, uint32_t addr) {
    asm volatile("ldmatrix.sync.aligned.m8n8.x4.shared.b16 {%0,%1,%2,%3}, [%4];"
                 : "=r"(r[0]), "=r"(r[1]), "=r"(r[2]), "=r"(r[3]) : "r"(addr));
}

__device__ __forceinline__ void mma_f32acc(float* c, const uint32_t* a, const uint32_t* b) {
    asm volatile("mma.sync.aligned.m16n8k16.row.col.f32.f16.f16.f32 "
                 "{%0,%1,%2,%3}, {%4,%5,%6,%7}, {%8,%9}, {%0,%1,%2,%3};"
                 : "+f"(c[0]), "+f"(c[1]), "+f"(c[2]), "+f"(c[3])
                 : "r"(a[0]), "r"(a[1]), "r"(a[2]), "r"(a[3]), "r"(b[0]), "r"(b[1]));
}

// ---------------------------------------------------------------------------
// Conversion passes
// ---------------------------------------------------------------------------
__global__ __launch_bounds__(256) void qconv_kernel(const float* __restrict__ in,
                                                    const float* __restrict__ sc) {
    size_t i = ((size_t)blockIdx.x * 256 + threadIdx.x) * 8;
    float4 a = *(const float4*)(in + i);
    float4 b = *(const float4*)(in + i + 4);
    float4 s0 = *(const float4*)(sc + (i & (D_ - 1)));
    float4 s1 = *(const float4*)(sc + ((i + 4) & (D_ - 1)));
    __half h[8] = {__float2half(a.x * s0.x), __float2half(a.y * s0.y),
                   __float2half(a.z * s0.z), __float2half(a.w * s0.w),
                   __float2half(b.x * s1.x), __float2half(b.y * s1.y),
                   __float2half(b.z * s1.z), __float2half(b.w * s1.w)};
    *(uint4*)(g_Qh + i) = *(uint4*)h;
}

// memory [LK,D] fp32 -> g_Mh [LK,D] fp16 AND g_MTh [D,LK] fp16, 32x32 tiles
__global__ __launch_bounds__(256) void mconv_kernel(const float* __restrict__ mem) {
    __shared__ float tile[32][33];
    const int d0 = blockIdx.x * 32;
    const int k0 = blockIdx.y * 32;
    const int bz = blockIdx.z;
    const int tx = threadIdx.x & 31;
    const int ty = threadIdx.x >> 5;  // 0..7
    const float* src = mem + (size_t)bz * LK_ * D_;
#pragma unroll
    for (int j = 0; j < 4; j++) {
        int kl = ty + j * 8;
        float v = src[(size_t)(k0 + kl) * D_ + d0 + tx];
        tile[kl][tx] = v;
        g_Mh[(size_t)bz * LK_ * D_ + (size_t)(k0 + kl) * D_ + d0 + tx] = __float2half(v);
    }
    __syncthreads();
#pragma unroll
    for (int j = 0; j < 4; j++) {
        int dl = ty + j * 8;
        g_MTh[(size_t)bz * D_ * LK_ + (size_t)(d0 + dl) * LK_ + k0 + tx] =
            __float2half(tile[tx][dl]);
    }
}

// ---------------------------------------------------------------------------
// fp16 warp-MMA GEMM (fp32 accumulate):
//   CTA tile 128(M) x 256(N), 512 threads = 16 warps, warp tile 32x64.
//   K-chunk 64, 4 smem stages, one barrier per iteration,
//   register-fragment ping-pong across k16 steps (hides LDSM latency).
// Rows padded to 144B: r*144 mod 128 cycles all 8 16B banks over 8 rows
// -> conflict-free ldmatrix without XOR swizzle.
// ---------------------------------------------------------------------------
#define ROWB  144
#define STG_A (128 * ROWB)                        // 18432
#define STG_B (256 * ROWB)                        // 36864
#define STAGE_BYTES (STG_A + STG_B)               // 55296
#define NSTAGE 4
#define GEMM_SMEM (NSTAGE * STAGE_BYTES)          // 221184

template <bool QK>
__global__ __launch_bounds__(512, 1) void gemm_kernel(float* __restrict__ outp) {
    constexpr int KDIM = QK ? D_ : LK_;      // contraction length
    constexpr int NDIM = QK ? LK_ : D_;      // output columns / B rows
    constexpr int NC   = KDIM / 64;          // K chunks

    extern __shared__ char smem_raw[];
    const uint32_t sb = smem_u32(smem_raw);

    const int t  = threadIdx.x;
    const int b  = blockIdx.z;
    const int m0 = blockIdx.y * 128;
    const int n0 = blockIdx.x * 256;

    const __half* Ap = (QK ? g_Qh : g_Ph)  + ((size_t)b * LQ_  + m0) * KDIM;
    const __half* Bp = (QK ? g_Mh : g_MTh) + ((size_t)b * NDIM + n0) * KDIM;

    float acc[2][8][4];
#pragma unroll
    for (int i = 0; i < 2; i++)
#pragma unroll
        for (int j = 0; j < 8; j++)
#pragma unroll
            for (int k = 0; k < 4; k++) acc[i][j][k] = 0.0f;

    // ---- async loader: chunk c -> stage c%4, 64 k-elems = 8 x 16B per row ----
    auto load_chunk = [&](int c) {
        const uint32_t st = sb + (c % NSTAGE) * STAGE_BYTES;
        const int koff = c * 64;
#pragma unroll
        for (int i = 0; i < 2; i++) {          // A: 128 rows x 8 chunks
            int id  = t + (i << 9);
            int row = id >> 3, ch = id & 7;
            uint32_t so = (uint32_t)(row * ROWB + ch * 16);
            cp16(st + so, Ap + (size_t)row * KDIM + koff + ch * 8);
        }
#pragma unroll
        for (int i = 0; i < 4; i++) {          // B: 256 rows x 8 chunks
            int id  = t + (i << 9);
            int row = id >> 3, ch = id & 7;
            uint32_t so = (uint32_t)(row * ROWB + ch * 16);
            cp16(st + STG_A + so, Bp + (size_t)row * KDIM + koff + ch * 8);
        }
        asm volatile("cp.async.commit_group;\n" ::: "memory");
    };

    const int lane = t & 31;
    const int w    = t >> 5;           // 0..15
    const int wm   = (w >> 2) * 32;    // warp M origin (4 x 32)
    const int wn   = (w & 3) * 64;     // warp N origin (4 x 64)

    const int a_row   = wm + (lane & 15);
    const int a_khalf = lane >> 4;                       // 0/1 -> k+0 / k+8
    const int b_row   = wn + (lane & 7) + ((lane >> 4) << 3);
    const int b_khalf = (lane >> 3) & 1;

    // prefill NSTAGE-1 stages; the 4th is loaded inside the loop
    load_chunk(0);
    load_chunk(1);
    load_chunk(2);

    uint32_t af[2][2][4], bf[2][4][4];   // ping-pong fragments

    for (int c = 0; c < NC; c++) {
        const int rem = NC - 1 - c;                 // chunks not yet computed
        if (rem >= 2)      asm volatile("cp.async.wait_group 2;\n" ::: "memory");
        else if (rem == 1) asm volatile("cp.async.wait_group 1;\n" ::: "memory");
        else               asm volatile("cp.async.wait_group 0;\n" ::: "memory");
        __syncthreads();   // single barrier: publishes stage c, proves stage c-1 consumed

        // refill the stage consumed last iteration
        if (c + NSTAGE - 1 < NC) load_chunk(c + NSTAGE - 1);

        const uint32_t stA = sb + (c % NSTAGE) * STAGE_BYTES;
        const uint32_t stB = stA + STG_A;
        const uint32_t aBase = stA + (uint32_t)(a_row * ROWB + a_khalf * 16);
        const uint32_t bBase = stB + (uint32_t)(b_row * ROWB + b_khalf * 16);

        // preload k16 = 0 fragments into buffer 0
#pragma unroll
        for (int j = 0; j < 4; j++) ldsm4(bf[0][j], bBase + j * (16 * ROWB));
#pragma unroll
        for (int i = 0; i < 2; i++) ldsm4(af[0][i], aBase + i * (16 * ROWB));

#pragma unroll
        for (int k16 = 0; k16 < 4; k16++) {
            const int cur = k16 & 1, nxt = cur ^ 1;
            if (k16 < 3) {   // issue next step's LDSM before current MMAs
                const uint32_t ao = aBase + (uint32_t)((k16 + 1) * 32);
                const uint32_t bo = bBase + (uint32_t)((k16 + 1) * 32);
#pragma unroll
                for (int j = 0; j < 4; j++) ldsm4(bf[nxt][j], bo + j * (16 * ROWB));
#pragma unroll
                for (int i = 0; i < 2; i++) ldsm4(af[nxt][i], ao + i * (16 * ROWB));
            }
#pragma unroll
            for (int i = 0; i < 2; i++)
#pragma unroll
                for (int jj = 0; jj < 8; jj++)
                    mma_f32acc(acc[i][jj], af[cur][i], &bf[cur][jj >> 1][(jj & 1) * 2]);
        }
    }

    // ---- epilogue ----
#pragma unroll
    for (int i = 0; i < 2; i++) {
        const int r0 = m0 + wm + i * 16 + (lane >> 2);
#pragma unroll
        for (int jj = 0; jj < 8; jj++) {
            const int col = n0 + wn + jj * 8 + (lane & 3) * 2;
            if (QK) {
                __half* Crow = g_Sh + (size_t)b * LQ_ * LK_;
                *(__half2*)(Crow + (size_t)r0 * NDIM + col) =
                    __floats2half2_rn(acc[i][jj][0], acc[i][jj][1]);
                *(__half2*)(Crow + (size_t)(r0 + 8) * NDIM + col) =
                    __floats2half2_rn(acc[i][jj][2], acc[i][jj][3]);
            } else {
                float* Crow = outp + (size_t)b * LQ_ * D_;
                *(float2*)(Crow + (size_t)r0 * NDIM + col) =
                    make_float2(acc[i][jj][0], acc[i][jj][1]);
                *(float2*)(Crow + (size_t)(r0 + 8) * NDIM + col) =
                    make_float2(acc[i][jj][2], acc[i][jj][3]);
            }
        }
    }
}

// ---------------------------------------------------------------------------
// Softmax: fp16 logits + mask (L2-resident) -> fp16 probability row
// ---------------------------------------------------------------------------
__global__ __launch_bounds__(256) void softmax_kernel(const float* __restrict__ mask) {
    const size_t row = blockIdx.x;
    const __half* p = g_Sh + row * LK_;
    const float* mrow = mask + (row >> 11) * LK_;   // row/LQ_ = batch
    const int tid = threadIdx.x;

    uint4 raw = *(const uint4*)(p + tid * 8);
    const __half2* hp = (const __half2*)&raw;
    float v[8];
#pragma unroll
    for (int j = 0; j < 4; j++) {
        float2 f = __half22float2(hp[j]);
        v[2 * j] = f.x; v[2 * j + 1] = f.y;
    }
    float4 mk0 = *(const float4*)(mrow + tid * 8);
    float4 mk1 = *(const float4*)(mrow + tid * 8 + 4);
    v[0] -= 1e30f * mk0.x; v[1] -= 1e30f * mk0.y;
    v[2] -= 1e30f * mk0.z; v[3] -= 1e30f * mk0.w;
    v[4] -= 1e30f * mk1.x; v[5] -= 1e30f * mk1.y;
    v[6] -= 1e30f * mk1.z; v[7] -= 1e30f * mk1.w;

    float m = v[0];
#pragma unroll
    for (int j = 1; j < 8; j++) m = fmaxf(m, v[j]);
#pragma unroll
    for (int o = 16; o > 0; o >>= 1) m = fmaxf(m, __shfl_xor_sync(0xffffffffu, m, o));

    __shared__ float red[8];
    const int warp = tid >> 5;
    if ((tid & 31) == 0) red[warp] = m;
    __syncthreads();
    m = red[0];
#pragma unroll
    for (int i = 1; i < 8; i++) m = fmaxf(m, red[i]);

    float s = 0.0f;
#pragma unroll
    for (int j = 0; j < 8; j++) { v[j] = __expf(v[j] - m); s += v[j]; }
#pragma unroll
    for (int o = 16; o > 0; o >>= 1) s += __shfl_xor_sync(0xffffffffu, s, o);

    __syncthreads();
    if ((tid & 31) == 0) red[warp] = s;
    __syncthreads();
    s = ((red[0] + red[1]) + (red[2] + red[3])) + ((red[4] + red[5]) + (red[6] + red[7]));

    const float inv = 1.0f / s;
    __half h[8];
#pragma unroll
    for (int j = 0; j < 8; j++) h[j] = __float2half(v[j] * inv);
    *(uint4*)(g_Ph + row * LK_ + tid * 8) = *(uint4*)h;
}

// ---------------------------------------------------------------------------
// inputs: 0=input 1=memory 2=mask 3=w_input (cancels in softmax) 4=dot_scale
// ---------------------------------------------------------------------------
extern "C" void kernel_launch(void* const* d_in, const int* in_sizes, int n_in,
                              void* d_out, int out_size) {
    const float* input     = (const float*)d_in[0];
    const float* memory    = (const float*)d_in[1];
    const float* mask      = (const float*)d_in[2];
    const float* dot_scale = (const float*)d_in[4];
    float* out = (float*)d_out;

    cudaFuncSetAttribute(gemm_kernel<true>,  cudaFuncAttributeMaxDynamicSharedMemorySize, GEMM_SMEM);
    cudaFuncSetAttribute(gemm_kernel<false>, cudaFuncAttributeMaxDynamicSharedMemorySize, GEMM_SMEM);

    qconv_kernel<<<(size_t)B_ * LQ_ * D_ / 2048, 256>>>(input, dot_scale);
    mconv_kernel<<<dim3(D_ / 32, LK_ / 32, B_), 256>>>(memory);

    gemm_kernel<true><<<dim3(LK_ / 256, LQ_ / 128, B_), 512, GEMM_SMEM>>>(nullptr);

    softmax_kernel<<<B_ * LQ_, 256>>>(mask);

    gemm_kernel<false><<<dim3(D_ / 256, LQ_ / 128, B_), 512, GEMM_SMEM>>>(out);
}